// round 8
// baseline (speedup 1.0000x reference)
#include <cuda_runtime.h>
#include <math.h>
#include <stdint.h>

#define Bn   128
#define Dd   512
#define Tt   33
#define Ll   32
#define Vv   10000
#define G4   2048

// ---------------- static device scratch ------------------------------------
__device__ float    g_X  [Tt * Bn * Dd];        // per-step inputs
__device__ float    g_Gx [2 * Tt * Bn * G4];    // x-side gates (both layers)
__device__ float    g_H  [Ll * Bn * Dd];        // normalized h history
__device__ float    g_hm [Bn * Dd];             // h after layer 0
__device__ float    g_hr [Bn * Dd];             // h after layer 1 (pre-LN)
__device__ float    g_rs [2][Bn];               // per-row sum   (parity buf)
__device__ float    g_rs2[2][Bn];               // per-row sumsq (parity buf)
__device__ unsigned g_barg[2];                  // per-group barrier counters
__device__ int      g_cap64;

// ---------------- utility kernels -------------------------------------------
__global__ void k_init() {
    int i = blockIdx.x * blockDim.x + threadIdx.x;
    if (i < Bn * Dd) g_hr[i] = 0.f;
    if (i < 2 * Bn) { ((float*)g_rs)[i] = 0.f; ((float*)g_rs2)[i] = 0.f; }
    if (i < 2) g_barg[i] = 0u;
}

// caption int64 vs int32 detection (values < 10000 => int64 high words all 0)
__global__ void k_detect(const int* __restrict__ cap) {
    int any = 0;
    for (int i = threadIdx.x; i < 2048; i += blockDim.x)
        if (cap[2 * i + 1] != 0) any = 1;
    any = __syncthreads_or(any);
    if (threadIdx.x == 0) g_cap64 = any ? 0 : 1;
}

__global__ void k_build_x(const float* __restrict__ features,
                          const void*  __restrict__ cap,
                          const float* __restrict__ embW) {
    int blk = blockIdx.x;
    int t = blk >> 7;
    int b = blk & 127;
    const float* src;
    if (t == 0) {
        src = features + (size_t)b * Dd;
    } else {
        long long idx;
        if (g_cap64) idx = ((const long long*)cap)[b * Ll + (t - 1)];
        else         idx = (long long)((const int*)cap)[b * Ll + (t - 1)];
        src = embW + (size_t)idx * Dd;
    }
    float4*       dst = (float4*)(g_X + ((size_t)t * Bn + b) * Dd);
    const float4* s4  = (const float4*)src;
    dst[threadIdx.x] = s4[threadIdx.x];
}

// ---------------- tf32 helpers (FC path) -------------------------------------
__device__ __forceinline__ unsigned f2t(float x) {
    unsigned r;
    asm("cvt.rna.tf32.f32 %0, %1;" : "=r"(r) : "f"(x));
    return r;
}

__device__ __forceinline__ void mma_tf32(float* c, const unsigned* a, const unsigned* b) {
    asm volatile(
        "mma.sync.aligned.m16n8k8.row.col.f32.tf32.tf32.f32 "
        "{%0,%1,%2,%3}, {%4,%5,%6,%7}, {%8,%9}, {%0,%1,%2,%3};\n"
        : "+f"(c[0]), "+f"(c[1]), "+f"(c[2]), "+f"(c[3])
        : "r"(a[0]), "r"(a[1]), "r"(a[2]), "r"(a[3]), "r"(b[0]), "r"(b[1]));
}

// ---------------- bf16 helpers -------------------------------------------------
__device__ __forceinline__ unsigned bpack(float e0, float e1) {
    unsigned r;
    asm("cvt.rn.bf16x2.f32 %0, %1, %2;" : "=r"(r) : "f"(e1), "f"(e0));
    return r;
}
__device__ __forceinline__ float blo(unsigned p) { return __uint_as_float(p << 16); }
__device__ __forceinline__ float bhi(unsigned p) { return __uint_as_float(p & 0xffff0000u); }

__device__ __forceinline__ void mma_bf16(float* c,
                                         unsigned a0, unsigned a1, unsigned a2, unsigned a3,
                                         unsigned b0, unsigned b1) {
    asm volatile(
        "mma.sync.aligned.m16n8k16.row.col.f32.bf16.bf16.f32 "
        "{%0,%1,%2,%3}, {%4,%5,%6,%7}, {%8,%9}, {%0,%1,%2,%3};\n"
        : "+f"(c[0]), "+f"(c[1]), "+f"(c[2]), "+f"(c[3])
        : "r"(a0), "r"(a1), "r"(a2), "r"(a3), "r"(b0), "r"(b1));
}

// ---------------- fast activations (saturation-safe) -------------------------
__device__ __forceinline__ float fsig(float x) {
    float e = __expf(-x);
    return __fdividef(1.f, 1.f + e);
}
__device__ __forceinline__ float ftanh(float x) {
    float e = __expf(2.f * x);
    return 1.f - __fdividef(2.f, e + 1.f);
}

// ---------------- fence-free per-group grid barrier ---------------------------
__device__ __forceinline__ void grid_barrier_grp(unsigned* bar, unsigned& target) {
    __syncthreads();
    if (threadIdx.x == 0) {
        target += 64u;
        asm volatile("red.release.gpu.global.add.u32 [%0], 1;" :: "l"(bar) : "memory");
        unsigned v;
        do {
            asm volatile("ld.acquire.gpu.global.u32 %0, [%1];" : "=r"(v) : "l"(bar) : "memory");
        } while (v < target);
    }
    __syncthreads();
}

// ---------------- persistent recurrence kernel -------------------------------
// 128 CTAs x 256 threads = 2 independent batch-groups (64 rows) x 64 j-groups.
// 2 phases/step: L0(GEMM+cell, LN applied inline on staging) | bar |
//                L1(GEMM+cell+row-sum atomics) | bar
// smem layout (bytes):
//   Bsm  uint2[2*32][258]   0      .. 132096
//   Asm  uint2[128][66]     132096 .. 199680
//   Cs   float[64][36]      199680 .. 208896
//   csm  float[64][8]       208896 .. 210944
//   lngs float[512]         210944 .. 212992
//   lnbs float[512]         212992 .. 215040
//   mus  float[64]          215040 .. 215296
//   rsds float[64]          215296 .. 215552
#define SMEM_REC 215552
__global__ void __launch_bounds__(256, 1)
k_recurrence(const float* __restrict__ Whh,
             const float* __restrict__ lng, const float* __restrict__ lnb) {
    extern __shared__ __align__(16) char sbuf[];
    uint2* Bsm       = (uint2*)sbuf;
    uint2 (*Asm)[66] = (uint2(*)[66])(sbuf + 132096);
    float (*Cs)[36]  = (float(*)[36])(sbuf + 199680);
    float (*csm)[8]  = (float(*)[8])(sbuf + 208896);
    float* lngs      = (float*)(sbuf + 210944);
    float* lnbs      = (float*)(sbuf + 212992);
    float* mus       = (float*)(sbuf + 215040);
    float* rsds      = (float*)(sbuf + 215296);

    const int tid  = threadIdx.x;
    const int lane = tid & 31;
    const int warp = tid >> 5;
    const int gid  = lane >> 2, t4 = lane & 3;
    const int cta  = blockIdx.x;
    const int grp  = cta >> 6;               // batch group 0/1
    const int jcta = cta & 63;               // j-group: cols [jcta*8, jcta*8+8)
    const int bm0  = grp * 64;
    const int wm   = warp >> 1, wn = warp & 1;
    unsigned* mybar = &g_barg[grp];
    unsigned target = 0;

    // ---- one-time: Whh slice (both layers) -> bf16 hi/lo pairs in smem ----
    for (int idx = tid; idx < 2 * 32 * 256; idx += 256) {
        int l  = idx >> 13;
        int rm = idx & 8191;
        int rl = rm >> 8;
        int kp = rm & 255;
        int p  = jcta * 32 + rl;
        int orig = ((p & 3) << 9) | (p >> 2);
        float2 v = *(const float2*)(Whh + ((size_t)l * G4 + orig) * Dd + kp * 2);
        unsigned h  = bpack(v.x, v.y);
        unsigned lo = bpack(v.x - blo(h), v.y - bhi(h));
        Bsm[(l * 32 + rl) * 258 + kp] = make_uint2(h, lo);
    }
    for (int i = tid; i < 64 * 8; i += 256) csm[i >> 3][i & 7] = 0.f;
    for (int i = tid; i < Dd; i += 256) { lngs[i] = lng[i]; lnbs[i] = lnb[i]; }
    __syncthreads();

    const int c4   = tid & 63;      // col-quad (constant per thread)
    const int row0 = tid >> 6;      // staging base row

    float gpre[2][4];
#define GXLOAD(PH)                                                        \
    {                                                                     \
        int tt = (PH) >> 1, ll = (PH) & 1;                                \
        const float* gxp = g_Gx + ((size_t)ll * Tt + tt) * Bn * G4;       \
        _Pragma("unroll")                                                 \
        for (int it = 0; it < 2; it++) {                                  \
            int x = tid + it * 256;                                       \
            int b = bm0 + (x >> 3);                                       \
            int j = jcta * 8 + (x & 7);                                   \
            gpre[it][0] = __ldg(&gxp[b * G4 + j]);                        \
            gpre[it][1] = __ldg(&gxp[b * G4 + 512 + j]);                  \
            gpre[it][2] = __ldg(&gxp[b * G4 + 1024 + j]);                 \
            gpre[it][3] = __ldg(&gxp[b * G4 + 1536 + j]);                 \
        }                                                                 \
    }

    GXLOAD(0)

#pragma unroll 1
    for (int ph = 0; ph < 2 * Tt; ph++) {
        const int t = ph >> 1, l = ph & 1;
        const float* Araw = (l == 0) ? g_hr : g_hm;
        float*       hout = (l == 0) ? g_hm : g_hr;
        const int    l32  = l * 32;
        const int    par_r = (t - 1) & 1;     // sums read (L0) / zeroed (L1)
        const int    par_w = t & 1;           // sums accumulated (L1)
        const bool   ln   = (l == 0) && (t > 0);

        if (ln && tid < 64) {
            float s  = __ldcg(&g_rs [par_r][bm0 + tid]);
            float s2 = __ldcg(&g_rs2[par_r][bm0 + tid]);
            float mu = s * (1.f / 512.f);
            float var = s2 * (1.f / 512.f) - mu * mu;
            mus[tid]  = mu;
            rsds[tid] = rsqrtf(var + 1e-5f);
        }
        if (l == 1 && jcta == 0 && tid < 64) {
            __stcg(&g_rs [par_r][bm0 + tid], 0.f);
            __stcg(&g_rs2[par_r][bm0 + tid], 0.f);
        }
        if (ln) __syncthreads();

        float accA[2][4], accB[2][4];
#pragma unroll
        for (int n = 0; n < 2; n++)
#pragma unroll
            for (int q = 0; q < 4; q++) { accA[n][q] = 0.f; accB[n][q] = 0.f; }

#pragma unroll 1
        for (int half = 0; half < 2; half++) {
            // ---- stage A half (LN applied inline on L0, t>0) ----
            const float* Ag = Araw + (size_t)bm0 * Dd + half * 256;
            float4 lg4, lb4;
            if (ln) {
                lg4 = *(float4*)&lngs[half * 256 + c4 * 4];
                lb4 = *(float4*)&lnbs[half * 256 + c4 * 4];
            }
#pragma unroll
            for (int r = 0; r < 16; r++) {
                int row = row0 + r * 4;
                float4 v = __ldcg((const float4*)(Ag + (size_t)row * Dd + c4 * 4));
                if (ln) {
                    float mu = mus[row], rd = rsds[row];
                    v.x = (v.x - mu) * rd * lg4.x + lb4.x;
                    v.y = (v.y - mu) * rd * lg4.y + lb4.y;
                    v.z = (v.z - mu) * rd * lg4.z + lb4.z;
                    v.w = (v.w - mu) * rd * lg4.w + lb4.w;
                    if (t >= 2 && jcta == (row >> 3))
                        *(float4*)&g_H[((size_t)(t - 2) * Bn + bm0 + row) * Dd
                                       + half * 256 + c4 * 4] = v;
                }
                unsigned h01 = bpack(v.x, v.y);
                unsigned h23 = bpack(v.z, v.w);
                unsigned l01 = bpack(v.x - blo(h01), v.y - bhi(h01));
                unsigned l23 = bpack(v.z - blo(h23), v.w - bhi(h23));
                Asm[c4 * 2    ][row] = make_uint2(h01, l01);
                Asm[c4 * 2 + 1][row] = make_uint2(h23, l23);
            }
            __syncthreads();

            const int mm = wm * 16 + gid;
            const int kpb = half * 128;
#pragma unroll
            for (int i = 0; i < 16; i++) {
                uint2 a0 = Asm[i * 8 + t4    ][mm];
                uint2 a1 = Asm[i * 8 + t4    ][mm + 8];
                uint2 a2 = Asm[i * 8 + t4 + 4][mm];
                uint2 a3 = Asm[i * 8 + t4 + 4][mm + 8];
#pragma unroll
                for (int nf = 0; nf < 2; nf++) {
                    int nn = wn * 16 + nf * 8 + gid;
                    uint2 b0 = Bsm[(l32 + nn) * 258 + kpb + i * 8 + t4    ];
                    uint2 b1 = Bsm[(l32 + nn) * 258 + kpb + i * 8 + t4 + 4];
                    mma_bf16(accA[nf], a0.x, a1.x, a2.x, a3.x, b0.x, b1.x);  // hi.hi
                    mma_bf16(accB[nf], a0.y, a1.y, a2.y, a3.y, b0.x, b1.x);  // lo.hi
                    mma_bf16(accB[nf], a0.x, a1.x, a2.x, a3.x, b0.y, b1.y);  // hi.lo
                }
            }
            __syncthreads();
        }
        // accumulators -> Cs
#pragma unroll
        for (int nf = 0; nf < 2; nf++) {
            int r0 = wm * 16 + gid;
            int c0 = wn * 16 + nf * 8 + 2 * t4;
            Cs[r0    ][c0    ] = accA[nf][0] + accB[nf][0];
            Cs[r0    ][c0 + 1] = accA[nf][1] + accB[nf][1];
            Cs[r0 + 8][c0    ] = accA[nf][2] + accB[nf][2];
            Cs[r0 + 8][c0 + 1] = accA[nf][3] + accB[nf][3];
        }
        __syncthreads();
        // ---- LSTM cell epilogue (gx preloaded); L1 adds row-sum atomics ----
#pragma unroll
        for (int it = 0; it < 2; it++) {
            int x    = tid + it * 256;
            int brow = x >> 3, jj = x & 7;
            int b    = bm0 + brow;
            int j    = jcta * 8 + jj;
            float gi = Cs[brow][jj * 4 + 0] + gpre[it][0];
            float gf = Cs[brow][jj * 4 + 1] + gpre[it][1];
            float gg = Cs[brow][jj * 4 + 2] + gpre[it][2];
            float go = Cs[brow][jj * 4 + 3] + gpre[it][3];
            float ii = fsig(gi);
            float ff = fsig(gf);
            float gt = ftanh(gg);
            float oo = fsig(go);
            float cn = ff * csm[brow][jj] + ii * gt;
            csm[brow][jj] = cn;
            float hv = oo * ftanh(cn);
            __stcg(&hout[(size_t)b * Dd + j], hv);
            if (l == 1) {
                float s = hv, s2 = hv * hv;
                s  += __shfl_xor_sync(0xffffffffu, s, 1);
                s2 += __shfl_xor_sync(0xffffffffu, s2, 1);
                s  += __shfl_xor_sync(0xffffffffu, s, 2);
                s2 += __shfl_xor_sync(0xffffffffu, s2, 2);
                s  += __shfl_xor_sync(0xffffffffu, s, 4);
                s2 += __shfl_xor_sync(0xffffffffu, s2, 4);
                if ((lane & 7) == 0) {
                    atomicAdd(&g_rs [par_w][b], s);
                    atomicAdd(&g_rs2[par_w][b], s2);
                }
            }
        }
        if (ph < 2 * Tt - 1) GXLOAD(ph + 1)
        grid_barrier_grp(mybar, target);
    }

    // ---- tail: history row for the last step (g_H[31] = LN(h at t=32)) ----
    {
        int row = cta;
        float v0 = __ldcg(&g_hr[(size_t)row * Dd + tid]);
        float v1 = __ldcg(&g_hr[(size_t)row * Dd + tid + 256]);
        float s  = __ldcg(&g_rs [0][row]);
        float s2 = __ldcg(&g_rs2[0][row]);
        float mu = s * (1.f / 512.f);
        float rd = rsqrtf(s2 * (1.f / 512.f) - mu * mu + 1e-5f);
        g_H[((size_t)31 * Bn + row) * Dd + tid]       = (v0 - mu) * rd * lngs[tid] + lnbs[tid];
        g_H[((size_t)31 * Bn + row) * Dd + tid + 256] = (v1 - mu) * rd * lngs[tid + 256] + lnbs[tid + 256];
    }
#undef GXLOAD
}

// ---------------- Gx GEMM, bf16x3:  C = A(MxK) * B(NxK)^T + b1 + b2 ----------
__global__ void __launch_bounds__(256)
gemm_gx_bf16(const float* __restrict__ A, int M, int lda,
             const float* __restrict__ Bm, int N, int ldb, int K,
             const float* __restrict__ bias1, const float* __restrict__ bias2,
             float* __restrict__ C, int ldc)
{
    __shared__ uint2 Ash[8][132];
    __shared__ uint2 Bsh[8][68];

    const int tid  = threadIdx.x;
    const int lane = tid & 31;
    const int warp = tid >> 5;
    const int wn = warp & 1, wm = warp >> 1;
    const int gid = lane >> 2, t4 = lane & 3;
    const int m0 = blockIdx.x * 128;
    const int n0 = blockIdx.y * 64;

    float acc[2][4][4];
#pragma unroll
    for (int i = 0; i < 2; i++)
#pragma unroll
        for (int j = 0; j < 4; j++)
#pragma unroll
            for (int q = 0; q < 4; q++) acc[i][j][q] = 0.f;

    float4 ra[2], rb;
    const int arow = tid >> 2,  acb = tid & 3;
    const int brow = (tid & 255) >> 2;
#define LOAD_T(K0)                                                           \
    {                                                                        \
        ra[0] = *(const float4*)(A + (size_t)(m0 + arow) * lda + (K0) + acb * 4);       \
        ra[1] = *(const float4*)(A + (size_t)(m0 + arow + 64) * lda + (K0) + acb * 4);  \
        rb    = *(const float4*)(Bm + (size_t)(n0 + brow) * ldb + (K0) + acb * 4);      \
    }

    LOAD_T(0)

    for (int k0 = 0; k0 < K; k0 += 16) {
#pragma unroll
        for (int i = 0; i < 2; i++) {
            unsigned h01 = bpack(ra[i].x, ra[i].y);
            unsigned h23 = bpack(ra[i].z, ra[i].w);
            unsigned l01 = bpack(ra[i].x - blo(h01), ra[i].y - bhi(h01));
            unsigned l23 = bpack(ra[i].z - blo(h23), ra[i].w - bhi(h23));
            Ash[acb * 2    ][arow + i * 64] = make_uint2(h01, l01);
            Ash[acb * 2 + 1][arow + i * 64] = make_uint2(h23, l23);
        }
        {
            unsigned h01 = bpack(rb.x, rb.y);
            unsigned h23 = bpack(rb.z, rb.w);
            unsigned l01 = bpack(rb.x - blo(h01), rb.y - bhi(h01));
            unsigned l23 = bpack(rb.z - blo(h23), rb.w - bhi(h23));
            Bsh[acb * 2    ][brow] = make_uint2(h01, l01);
            Bsh[acb * 2 + 1][brow] = make_uint2(h23, l23);
        }
        __syncthreads();

        if (k0 + 16 < K) LOAD_T(k0 + 16)

        uint2 a0[2], a1[2], a2[2], a3[2];
#pragma unroll
        for (int mf = 0; mf < 2; mf++) {
            int mm = wm * 32 + mf * 16 + gid;
            a0[mf] = Ash[t4    ][mm];
            a1[mf] = Ash[t4    ][mm + 8];
            a2[mf] = Ash[t4 + 4][mm];
            a3[mf] = Ash[t4 + 4][mm + 8];
        }
#pragma unroll
        for (int nf = 0; nf < 4; nf++) {
            int nn = wn * 32 + nf * 8 + gid;
            uint2 b0 = Bsh[t4    ][nn];
            uint2 b1 = Bsh[t4 + 4][nn];
#pragma unroll
            for (int mf = 0; mf < 2; mf++) {
                mma_bf16(acc[mf][nf], a0[mf].x, a1[mf].x, a2[mf].x, a3[mf].x, b0.x, b1.x);
                mma_bf16(acc[mf][nf], a0[mf].y, a1[mf].y, a2[mf].y, a3[mf].y, b0.x, b1.x);
                mma_bf16(acc[mf][nf], a0[mf].x, a1[mf].x, a2[mf].x, a3[mf].x, b0.y, b1.y);
            }
        }
        __syncthreads();
    }

#pragma unroll
    for (int mf = 0; mf < 2; mf++)
#pragma unroll
        for (int nf = 0; nf < 4; nf++) {
            int r0 = m0 + wm * 32 + mf * 16 + gid;
            int c0 = n0 + wn * 32 + nf * 8 + 2 * t4;
#pragma unroll
            for (int q = 0; q < 4; q++) {
                int r = r0 + ((q >= 2) ? 8 : 0);
                int c = c0 + (q & 1);
                C[(size_t)r * ldc + c] = acc[mf][nf][q] + bias1[c] + bias2[c];
            }
        }
#undef LOAD_T
}

// ---------------- FC GEMM (tf32 single): permuted store ----------------------
template<int BM, int BN, int WM, int WN>
__global__ void __launch_bounds__(WM * WN * 32)
gemm_fc(const float* __restrict__ A, int M, int lda,
        const float* __restrict__ Bm, int N, int ldb, int K,
        const float* __restrict__ bias1,
        float* __restrict__ C, int ldc)
{
    constexpr int THREADS = WM * WN * 32;
    constexpr int PAD = 4;
    constexpr int MF = 2, NF = 4;

    __shared__ unsigned Ash[16][BM + PAD];
    __shared__ unsigned Bsh[16][BN + PAD];

    const int tid  = threadIdx.x;
    const int lane = tid & 31;
    const int warp = tid >> 5;
    const int wn = warp % WN, wm = warp / WN;
    const int gid = lane >> 2, t4 = lane & 3;
    const int m0 = blockIdx.x * BM;
    const int n0 = blockIdx.y * BN;

    float acc[MF][NF][4];
#pragma unroll
    for (int i = 0; i < MF; i++)
#pragma unroll
        for (int j = 0; j < NF; j++)
#pragma unroll
            for (int q = 0; q < 4; q++) acc[i][j][q] = 0.f;

    constexpr int LA = (BM * 16) / (THREADS * 4);
    constexpr int LB = (BN * 16) / (THREADS * 4);

    float4 ra[LA], rb[LB];

#define LOAD_T(K0)                                                          \
    {                                                                       \
        _Pragma("unroll")                                                   \
        for (int i = 0; i < LA; i++) {                                      \
            int f4 = tid + i * THREADS;                                     \
            int row = f4 >> 2, cb = f4 & 3;                                 \
            int gm = m0 + row;                                              \
            ra[i] = make_float4(0.f, 0.f, 0.f, 0.f);                        \
            if (gm < M) ra[i] = *(const float4*)(A + (size_t)gm * lda + (K0) + cb * 4); \
        }                                                                   \
        _Pragma("unroll")                                                   \
        for (int i = 0; i < LB; i++) {                                      \
            int f4 = tid + i * THREADS;                                     \
            int row = f4 >> 2, cb = f4 & 3;                                 \
            int grow = n0 + row;                                            \
            rb[i] = make_float4(0.f, 0.f, 0.f, 0.f);                        \
            if (grow < N) rb[i] = *(const float4*)(Bm + (size_t)grow * ldb + (K0) + cb * 4); \
        }                                                                   \
    }

    LOAD_T(0)

    for (int k0 = 0; k0 < K; k0 += 16) {
#pragma unroll
        for (int i = 0; i < LA; i++) {
            int f4 = tid + i * THREADS;
            int row = f4 >> 2, cb = f4 & 3;
            Ash[cb * 4 + 0][row] = f2t(ra[i].x);
            Ash[cb * 4 + 1][row] = f2t(ra[i].y);
            Ash[cb * 4 + 2][row] = f2t(ra[i].z);
            Ash[cb * 4 + 3][row] = f2t(ra[i].w);
        }
#pragma unroll
        for (int i = 0; i < LB; i++) {
            int f4 = tid + i * THREADS;
            int row = f4 >> 2, cb = f4 & 3;
            Bsh[cb * 4 + 0][row] = f2t(rb[i].x);
            Bsh[cb * 4 + 1][row] = f2t(rb[i].y);
            Bsh[cb * 4 + 2][row] = f2t(rb[i].z);
            Bsh[cb * 4 + 3][row] = f2t(rb[i].w);
        }
        __syncthreads();

        if (k0 + 16 < K) LOAD_T(k0 + 16)

#pragma unroll
        for (int ks = 0; ks < 2; ks++) {
            const int kb = ks * 8;
            unsigned ah[MF][4], bh[NF][2];
#pragma unroll
            for (int mf = 0; mf < MF; mf++) {
                int mm = wm * 32 + mf * 16 + gid;
                ah[mf][0] = Ash[kb + t4    ][mm];
                ah[mf][1] = Ash[kb + t4    ][mm + 8];
                ah[mf][2] = Ash[kb + t4 + 4][mm];
                ah[mf][3] = Ash[kb + t4 + 4][mm + 8];
            }
#pragma unroll
            for (int nf = 0; nf < NF; nf++) {
                int nn = wn * 32 + nf * 8 + gid;
                bh[nf][0] = Bsh[kb + t4    ][nn];
                bh[nf][1] = Bsh[kb + t4 + 4][nn];
            }
#pragma unroll
            for (int mf = 0; mf < MF; mf++)
#pragma unroll
                for (int nf = 0; nf < NF; nf++)
                    mma_tf32(acc[mf][nf], ah[mf], bh[nf]);
        }
        __syncthreads();
    }

#pragma unroll
    for (int mf = 0; mf < MF; mf++)
#pragma unroll
        for (int nf = 0; nf < NF; nf++) {
            int r0 = m0 + wm * 32 + mf * 16 + gid;
            int c0 = n0 + wn * 32 + nf * 8 + 2 * t4;
#pragma unroll
            for (int q = 0; q < 4; q++) {
                int r = r0 + ((q >= 2) ? 8 : 0);
                int c = c0 + (q & 1);
                if (r < M && c < N) {
                    int orow = (r & 127) * Ll + (r >> 7);
                    C[(size_t)orow * ldc + c] = acc[mf][nf][q] + bias1[c];
                }
            }
        }
#undef LOAD_T
}

// ---------------- in-place log_softmax, rows of 10000 ------------------------
__global__ void k_lsm(float* __restrict__ out) {
    __shared__ float row[Vv];
    __shared__ float red[8];
    float* p = out + (size_t)blockIdx.x * Vv;
    int tid = threadIdx.x;

    float mx = -1e30f;
    float4*       r4 = (float4*)row;
    const float4* p4 = (const float4*)p;
    for (int i = tid; i < Vv / 4; i += 256) {
        float4 v = p4[i];
        r4[i] = v;
        mx = fmaxf(mx, fmaxf(fmaxf(v.x, v.y), fmaxf(v.z, v.w)));
    }
#pragma unroll
    for (int o = 16; o > 0; o >>= 1) mx = fmaxf(mx, __shfl_xor_sync(0xffffffffu, mx, o));
    if ((tid & 31) == 0) red[tid >> 5] = mx;
    __syncthreads();
    mx = red[0];
#pragma unroll
    for (int i = 1; i < 8; i++) mx = fmaxf(mx, red[i]);

    float s = 0.f;
    for (int i = tid; i < Vv; i += 256) s += expf(row[i] - mx);
#pragma unroll
    for (int o = 16; o > 0; o >>= 1) s += __shfl_xor_sync(0xffffffffu, s, o);
    __syncthreads();
    if ((tid & 31) == 0) red[tid >> 5] = s;
    __syncthreads();
    s = red[0] + red[1] + red[2] + red[3] + red[4] + red[5] + red[6] + red[7];
    float lse = mx + logf(s);

    for (int i = tid; i < Vv; i += 256) p[i] = row[i] - lse;
}

// ---------------- host launcher ----------------------------------------------
extern "C" void kernel_launch(void* const* d_in, const int* in_sizes, int n_in,
                              void* d_out, int out_size) {
    const float* features = (const float*)d_in[0];
    const void*  caption  = d_in[1];
    const float* embW     = (const float*)d_in[2];
    const float* Wih      = (const float*)d_in[3];
    const float* Whh      = (const float*)d_in[4];
    const float* bih      = (const float*)d_in[5];
    const float* bhh      = (const float*)d_in[6];
    const float* lng      = (const float*)d_in[7];
    const float* lnb      = (const float*)d_in[8];
    const float* fcW      = (const float*)d_in[9];
    const float* fcb      = (const float*)d_in[10];
    float*       out      = (float*)d_out;

    float *pX, *pGx, *pH;
    cudaGetSymbolAddress((void**)&pX,  g_X);
    cudaGetSymbolAddress((void**)&pGx, g_Gx);
    cudaGetSymbolAddress((void**)&pH,  g_H);

    cudaFuncSetAttribute(k_recurrence,
                         cudaFuncAttributeMaxDynamicSharedMemorySize, SMEM_REC);

    k_init<<<256, 256>>>();
    k_detect<<<1, 256>>>((const int*)caption);
    k_build_x<<<Tt * Bn, 128>>>(features, caption, embW);

    // Gx = X @ Wih^T + bih + bhh   (both layers, bf16x3)
    for (int l = 0; l < 2; l++)
        gemm_gx_bf16<<<dim3(33, 32), 256>>>(
            pX, Tt * Bn, Dd,
            Wih + (size_t)l * G4 * Dd, G4, Dd, Dd,
            bih + l * G4, bhh + l * G4,
            pGx + (size_t)l * Tt * Bn * G4, G4);

    // full 33-step recurrence in ONE persistent kernel (single wave)
    k_recurrence<<<128, 256, SMEM_REC>>>(Whh, lng, lnb);

    // FC: logits = H @ fcW^T + fcb  (single tf32, permuted store)
    gemm_fc<128, 64, 4, 2><<<dim3(32, 157), 256>>>(
        pH, Ll * Bn, Dd, fcW, Vv, Dd, Dd,
        fcb, out, Vv);

    k_lsm<<<Ll * Bn, 256>>>(out);
}

// round 9
// speedup vs baseline: 1.0236x; 1.0236x over previous
#include <cuda_runtime.h>
#include <math.h>
#include <stdint.h>

#define Bn   128
#define Dd   512
#define Tt   33
#define Ll   32
#define Vv   10000
#define G4   2048
#define NFCT (32 * 157)          // FC tiles: 32 tau-blocks x 157 n-blocks

// ---------------- static device scratch ------------------------------------
__device__ float    g_X  [Tt * Bn * Dd];        // per-step inputs
__device__ float    g_Gx [2 * Tt * Bn * G4];    // x-side gates (both layers)
__device__ float    g_H  [Ll * Bn * Dd];        // normalized h history
__device__ float    g_h  [Bn * Dd];             // carried h (normalized)
__device__ float    g_hm [Bn * Dd];             // h after layer 0
__device__ float    g_hr [Bn * Dd];             // h after layer 1 (pre-LN)
__device__ unsigned g_bar;                      // grid barrier counter
__device__ unsigned g_fc;                       // FC tile work-stealing counter
__device__ int      g_cap64;

// ---------------- utility kernels -------------------------------------------
__global__ void k_init() {
    int i = blockIdx.x * blockDim.x + threadIdx.x;
    if (i < Bn * Dd) g_h[i] = 0.f;
    if (i == 0) { g_bar = 0u; g_fc = 0u; }
}

// caption int64 vs int32 detection (values < 10000 => int64 high words all 0)
__global__ void k_detect(const int* __restrict__ cap) {
    int any = 0;
    for (int i = threadIdx.x; i < 2048; i += blockDim.x)
        if (cap[2 * i + 1] != 0) any = 1;
    any = __syncthreads_or(any);
    if (threadIdx.x == 0) g_cap64 = any ? 0 : 1;
}

__global__ void k_build_x(const float* __restrict__ features,
                          const void*  __restrict__ cap,
                          const float* __restrict__ embW) {
    int blk = blockIdx.x;
    int t = blk >> 7;
    int b = blk & 127;
    const float* src;
    if (t == 0) {
        src = features + (size_t)b * Dd;
    } else {
        long long idx;
        if (g_cap64) idx = ((const long long*)cap)[b * Ll + (t - 1)];
        else         idx = (long long)((const int*)cap)[b * Ll + (t - 1)];
        src = embW + (size_t)idx * Dd;
    }
    float4*       dst = (float4*)(g_X + ((size_t)t * Bn + b) * Dd);
    const float4* s4  = (const float4*)src;
    dst[threadIdx.x] = s4[threadIdx.x];
}

// ---------------- tf32 helpers (FC path) -------------------------------------
__device__ __forceinline__ unsigned f2t(float x) {
    unsigned r;
    asm("cvt.rna.tf32.f32 %0, %1;" : "=r"(r) : "f"(x));
    return r;
}

__device__ __forceinline__ void mma_tf32(float* c, const unsigned* a, const unsigned* b) {
    asm volatile(
        "mma.sync.aligned.m16n8k8.row.col.f32.tf32.tf32.f32 "
        "{%0,%1,%2,%3}, {%4,%5,%6,%7}, {%8,%9}, {%0,%1,%2,%3};\n"
        : "+f"(c[0]), "+f"(c[1]), "+f"(c[2]), "+f"(c[3])
        : "r"(a[0]), "r"(a[1]), "r"(a[2]), "r"(a[3]), "r"(b[0]), "r"(b[1]));
}

// ---------------- bf16 helpers -------------------------------------------------
__device__ __forceinline__ unsigned bpack(float e0, float e1) {
    unsigned r;
    asm("cvt.rn.bf16x2.f32 %0, %1, %2;" : "=r"(r) : "f"(e1), "f"(e0));
    return r;
}
__device__ __forceinline__ float blo(unsigned p) { return __uint_as_float(p << 16); }
__device__ __forceinline__ float bhi(unsigned p) { return __uint_as_float(p & 0xffff0000u); }

__device__ __forceinline__ void mma_bf16(float* c,
                                         unsigned a0, unsigned a1, unsigned a2, unsigned a3,
                                         unsigned b0, unsigned b1) {
    asm volatile(
        "mma.sync.aligned.m16n8k16.row.col.f32.bf16.bf16.f32 "
        "{%0,%1,%2,%3}, {%4,%5,%6,%7}, {%8,%9}, {%0,%1,%2,%3};\n"
        : "+f"(c[0]), "+f"(c[1]), "+f"(c[2]), "+f"(c[3])
        : "r"(a0), "r"(a1), "r"(a2), "r"(a3), "r"(b0), "r"(b1));
}

// ---------------- fast activations (saturation-safe) -------------------------
__device__ __forceinline__ float fsig(float x) {
    float e = __expf(-x);
    return __fdividef(1.f, 1.f + e);
}
__device__ __forceinline__ float ftanh(float x) {
    float e = __expf(2.f * x);
    return 1.f - __fdividef(2.f, e + 1.f);
}

// ---------------- fence-free grid barrier (128 recurrence CTAs) --------------
__device__ __forceinline__ void grid_barrier(unsigned& target) {
    __syncthreads();
    if (threadIdx.x == 0) {
        target += 128u;
        unsigned* bar = &g_bar;
        asm volatile("red.release.gpu.global.add.u32 [%0], 1;" :: "l"(bar) : "memory");
        unsigned v;
        do {
            asm volatile("ld.acquire.gpu.global.u32 %0, [%1];" : "=r"(v) : "l"(bar) : "memory");
        } while (v < target);
    }
    __syncthreads();
}

// ---------------- FC tile worker (device-side, work-stealing) -----------------
// One tile: out-permuted C[tau-block, n-block] = H[128 rows] @ fcW^T + fcb.
// Gated on the recurrence barrier counter: g_H[tau] final once
// g_bar >= 128*(3*tau+6)  (LN phase of step tau+1 completed).
__device__ void fc_tiles(char* sbuf,
                         const float* __restrict__ fcW,
                         const float* __restrict__ fcb,
                         float* __restrict__ out) {
    unsigned (*Ash)[132] = (unsigned(*)[132])sbuf;            //  0   .. 8448
    unsigned (*Bsh)[68]  = (unsigned(*)[68])(sbuf + 8448);    // 8448 .. 12800
    volatile int* bcast  = (volatile int*)(sbuf + 12800);

    const int tid  = threadIdx.x;
    const int lane = tid & 31;
    const int warp = tid >> 5;
    const int wn = warp & 1, wm = warp >> 1;   // 4x2 warps
    const int gid = lane >> 2, t4 = lane & 3;

    for (;;) {
        if (tid == 0) {
            int id = (int)atomicAdd(&g_fc, 1u);
            if (id < NFCT) {
                unsigned need = 128u * (3u * (unsigned)(id / 157) + 6u);
                unsigned* bar = &g_bar;
                unsigned v;
                do {
                    asm volatile("ld.acquire.gpu.global.u32 %0, [%1];" : "=r"(v) : "l"(bar) : "memory");
                } while (v < need);
            }
            *bcast = id;
        }
        __syncthreads();
        int id = *bcast;
        __syncthreads();
        if (id >= NFCT) return;

        const int m0 = (id / 157) * 128;
        const int n0 = (id % 157) * 64;

        float acc[2][4][4];
#pragma unroll
        for (int i = 0; i < 2; i++)
#pragma unroll
            for (int j = 0; j < 4; j++)
#pragma unroll
                for (int q = 0; q < 4; q++) acc[i][j][q] = 0.f;

        float4 ra[2], rb;
        const int arow = tid >> 2, acb = tid & 3;   // A: 2 rows/thread (0..63,+64)
        const int brow = arow;                      // B: 1 row/thread
#define FCLOAD(K0)                                                                 \
        {                                                                          \
            ra[0] = *(const float4*)(g_H + (size_t)(m0 + arow) * Dd + (K0) + acb * 4);      \
            ra[1] = *(const float4*)(g_H + (size_t)(m0 + arow + 64) * Dd + (K0) + acb * 4); \
            rb = make_float4(0.f, 0.f, 0.f, 0.f);                                  \
            if (n0 + brow < Vv)                                                    \
                rb = *(const float4*)(fcW + (size_t)(n0 + brow) * Dd + (K0) + acb * 4);     \
        }

        FCLOAD(0)

        for (int k0 = 0; k0 < Dd; k0 += 16) {
#pragma unroll
            for (int i = 0; i < 2; i++) {
                Ash[acb * 4 + 0][arow + i * 64] = f2t(ra[i].x);
                Ash[acb * 4 + 1][arow + i * 64] = f2t(ra[i].y);
                Ash[acb * 4 + 2][arow + i * 64] = f2t(ra[i].z);
                Ash[acb * 4 + 3][arow + i * 64] = f2t(ra[i].w);
            }
            Bsh[acb * 4 + 0][brow] = f2t(rb.x);
            Bsh[acb * 4 + 1][brow] = f2t(rb.y);
            Bsh[acb * 4 + 2][brow] = f2t(rb.z);
            Bsh[acb * 4 + 3][brow] = f2t(rb.w);
            __syncthreads();

            if (k0 + 16 < Dd) FCLOAD(k0 + 16)

#pragma unroll
            for (int ks = 0; ks < 2; ks++) {
                const int kb = ks * 8;
                unsigned ah[2][4], bh[4][2];
#pragma unroll
                for (int mf = 0; mf < 2; mf++) {
                    int mm = wm * 32 + mf * 16 + gid;
                    ah[mf][0] = Ash[kb + t4    ][mm];
                    ah[mf][1] = Ash[kb + t4    ][mm + 8];
                    ah[mf][2] = Ash[kb + t4 + 4][mm];
                    ah[mf][3] = Ash[kb + t4 + 4][mm + 8];
                }
#pragma unroll
                for (int nf = 0; nf < 4; nf++) {
                    int nn = wn * 32 + nf * 8 + gid;
                    bh[nf][0] = Bsh[kb + t4    ][nn];
                    bh[nf][1] = Bsh[kb + t4 + 4][nn];
                }
#pragma unroll
                for (int mf = 0; mf < 2; mf++)
#pragma unroll
                    for (int nf = 0; nf < 4; nf++)
                        mma_tf32(acc[mf][nf], ah[mf], bh[nf]);
            }
            __syncthreads();
        }

#pragma unroll
        for (int mf = 0; mf < 2; mf++)
#pragma unroll
            for (int nf = 0; nf < 4; nf++) {
                int r0 = m0 + wm * 32 + mf * 16 + gid;
                int c0 = n0 + wn * 32 + nf * 8 + 2 * t4;
#pragma unroll
                for (int q = 0; q < 4; q++) {
                    int r = r0 + ((q >= 2) ? 8 : 0);
                    int c = c0 + (q & 1);
                    if (c < Vv) {
                        int orow = (r & 127) * Ll + (r >> 7);
                        out[(size_t)orow * Vv + c] = acc[mf][nf][q] + fcb[c];
                    }
                }
            }
#undef FCLOAD
    }
}

// ---------------- persistent recurrence + FC kernel ---------------------------
// 148 CTAs x 256 threads. CTAs 0-127: recurrence (2 batch-groups x 64 j-groups,
// R7 structure). CTAs 128-147: FC workers from the start; recurrence CTAs join
// the FC tile pool when done.
// smem layout (bytes):
//   Bsm  uint2[2*32][258]   0      .. 132096
//   Asm  uint2[128][66]     132096 .. 199680
//   Cs   float[64][36]      199680 .. 208896
//   csm  float[64][8]       208896 .. 210944
//   red  float[8]           210944 .. 210976
#define SMEM_REC 210976
__global__ void __launch_bounds__(256, 1)
k_recurrence(const float* __restrict__ Whh,
             const float* __restrict__ lng, const float* __restrict__ lnb,
             const float* __restrict__ fcW, const float* __restrict__ fcb,
             float* __restrict__ out) {
    extern __shared__ __align__(16) char sbuf[];

    const int cta = blockIdx.x;
    if (cta >= 128) {                      // dedicated FC workers
        fc_tiles(sbuf, fcW, fcb, out);
        return;
    }

    uint2* Bsm       = (uint2*)sbuf;
    uint2 (*Asm)[66] = (uint2(*)[66])(sbuf + 132096);
    float (*Cs)[36]  = (float(*)[36])(sbuf + 199680);
    float (*csm)[8]  = (float(*)[8])(sbuf + 208896);
    float* red       = (float*)(sbuf + 210944);

    const int tid  = threadIdx.x;
    const int lane = tid & 31;
    const int warp = tid >> 5;
    const int gid  = lane >> 2, t4 = lane & 3;
    const int jcta = cta & 63;               // j-group: cols [jcta*8, jcta*8+8)
    const int bm0  = (cta >> 6) * 64;        // batch-group base row
    const int wm   = warp >> 1, wn = warp & 1;  // 4x2 warps, warp tile 16x16
    unsigned target = 0;

    // ---- one-time: Whh slice (both layers) -> bf16 hi/lo pairs in smem ----
    for (int idx = tid; idx < 2 * 32 * 256; idx += 256) {
        int l  = idx >> 13;
        int rm = idx & 8191;
        int rl = rm >> 8;
        int kp = rm & 255;
        int p  = jcta * 32 + rl;
        int orig = ((p & 3) << 9) | (p >> 2);
        float2 v = *(const float2*)(Whh + ((size_t)l * G4 + orig) * Dd + kp * 2);
        unsigned h  = bpack(v.x, v.y);
        unsigned lo = bpack(v.x - blo(h), v.y - bhi(h));
        Bsm[(l * 32 + rl) * 258 + kp] = make_uint2(h, lo);
    }
    for (int i = tid; i < 64 * 8; i += 256) csm[i >> 3][i & 7] = 0.f;
    float lg0 = lng[tid], lg1 = lng[tid + 256];
    float lb0 = lnb[tid], lb1 = lnb[tid + 256];
    __syncthreads();

    float gpre[2][4];
#define GXLOAD(TT, LL)                                                    \
    {                                                                     \
        const float* gxp = g_Gx + ((size_t)(LL) * Tt + (TT)) * Bn * G4;   \
        _Pragma("unroll")                                                 \
        for (int it = 0; it < 2; it++) {                                  \
            int x = tid + it * 256;                                       \
            int b = bm0 + (x >> 3);                                       \
            int j = jcta * 8 + (x & 7);                                   \
            gpre[it][0] = __ldg(&gxp[b * G4 + j]);                        \
            gpre[it][1] = __ldg(&gxp[b * G4 + 512 + j]);                  \
            gpre[it][2] = __ldg(&gxp[b * G4 + 1024 + j]);                 \
            gpre[it][3] = __ldg(&gxp[b * G4 + 1536 + j]);                 \
        }                                                                 \
    }

    GXLOAD(0, 0)

    for (int t = 0; t < Tt; t++) {
#pragma unroll 1
        for (int l = 0; l < 2; l++) {
            const float* A    = (l == 0) ? g_h : g_hm;
            float*       hout = (l == 0) ? g_hm : g_hr;
            const int    l32  = l * 32;

            float accA[2][4], accB[2][4];
#pragma unroll
            for (int n = 0; n < 2; n++)
#pragma unroll
                for (int q = 0; q < 4; q++) { accA[n][q] = 0.f; accB[n][q] = 0.f; }

#pragma unroll 1
            for (int half = 0; half < 2; half++) {
                // ---- stage A half: 64 rows x 256 k -> bf16 hi/lo pairs ----
                const float* Ag = A + (size_t)bm0 * Dd + half * 256;
#pragma unroll
                for (int r = 0; r < 16; r++) {
                    int idx = tid + r * 256;
                    int row = idx >> 6, c4 = idx & 63;
                    float4 v = __ldcg((const float4*)(Ag + (size_t)row * Dd + c4 * 4));
                    unsigned h01 = bpack(v.x, v.y);
                    unsigned h23 = bpack(v.z, v.w);
                    unsigned l01 = bpack(v.x - blo(h01), v.y - bhi(h01));
                    unsigned l23 = bpack(v.z - blo(h23), v.w - bhi(h23));
                    Asm[c4 * 2    ][row] = make_uint2(h01, l01);
                    Asm[c4 * 2 + 1][row] = make_uint2(h23, l23);
                }
                __syncthreads();

                const int mm = wm * 16 + gid;
                const int kpb = half * 128;
#pragma unroll
                for (int i = 0; i < 16; i++) {
                    uint2 a0 = Asm[i * 8 + t4    ][mm];
                    uint2 a1 = Asm[i * 8 + t4    ][mm + 8];
                    uint2 a2 = Asm[i * 8 + t4 + 4][mm];
                    uint2 a3 = Asm[i * 8 + t4 + 4][mm + 8];
#pragma unroll
                    for (int nf = 0; nf < 2; nf++) {
                        int nn = wn * 16 + nf * 8 + gid;
                        uint2 b0 = Bsm[(l32 + nn) * 258 + kpb + i * 8 + t4    ];
                        uint2 b1 = Bsm[(l32 + nn) * 258 + kpb + i * 8 + t4 + 4];
                        mma_bf16(accA[nf], a0.x, a1.x, a2.x, a3.x, b0.x, b1.x);  // hi.hi
                        mma_bf16(accB[nf], a0.y, a1.y, a2.y, a3.y, b0.x, b1.x);  // lo.hi
                        mma_bf16(accB[nf], a0.x, a1.x, a2.x, a3.x, b0.y, b1.y);  // hi.lo
                    }
                }
                __syncthreads();
            }
            // accumulators -> Cs
#pragma unroll
            for (int nf = 0; nf < 2; nf++) {
                int r0 = wm * 16 + gid;
                int c0 = wn * 16 + nf * 8 + 2 * t4;
                Cs[r0    ][c0    ] = accA[nf][0] + accB[nf][0];
                Cs[r0    ][c0 + 1] = accA[nf][1] + accB[nf][1];
                Cs[r0 + 8][c0    ] = accA[nf][2] + accB[nf][2];
                Cs[r0 + 8][c0 + 1] = accA[nf][3] + accB[nf][3];
            }
            __syncthreads();
            // LSTM cell: 64x8 = 512 elements, 2 per thread (gx preloaded)
#pragma unroll
            for (int it = 0; it < 2; it++) {
                int x    = tid + it * 256;
                int brow = x >> 3, jj = x & 7;
                int b    = bm0 + brow;
                int j    = jcta * 8 + jj;
                float gi = Cs[brow][jj * 4 + 0] + gpre[it][0];
                float gf = Cs[brow][jj * 4 + 1] + gpre[it][1];
                float gg = Cs[brow][jj * 4 + 2] + gpre[it][2];
                float go = Cs[brow][jj * 4 + 3] + gpre[it][3];
                float ii = fsig(gi);
                float ff = fsig(gf);
                float gt = ftanh(gg);
                float oo = fsig(go);
                float cn = ff * csm[brow][jj] + ii * gt;
                csm[brow][jj] = cn;
                __stcg(&hout[(size_t)b * Dd + j], oo * ftanh(cn));
            }
            // prefetch gx for the NEXT layer-phase before the barrier spin
            if (l == 0) { GXLOAD(t, 1) }
            else if (t + 1 < Tt) { GXLOAD(t + 1, 0) }
            grid_barrier(target);
        }
        // ---- LayerNorm: CTA handles batch row b = cta (256 threads, 2 elems) --
        {
            const float* xr = g_hr + (size_t)cta * Dd;
            float v0 = __ldcg(&xr[tid]), v1 = __ldcg(&xr[tid + 256]);
            float s = v0 + v1;
#pragma unroll
            for (int o = 16; o > 0; o >>= 1) s += __shfl_xor_sync(0xffffffffu, s, o);
            if (lane == 0) red[warp] = s;
            __syncthreads();
            float mu = (red[0] + red[1] + red[2] + red[3] +
                        red[4] + red[5] + red[6] + red[7]) * (1.f / 512.f);
            __syncthreads();
            float d0 = v0 - mu, d1 = v1 - mu;
            float vv = d0 * d0 + d1 * d1;
#pragma unroll
            for (int o = 16; o > 0; o >>= 1) vv += __shfl_xor_sync(0xffffffffu, vv, o);
            if (lane == 0) red[warp] = vv;
            __syncthreads();
            float var  = (red[0] + red[1] + red[2] + red[3] +
                          red[4] + red[5] + red[6] + red[7]) * (1.f / 512.f);
            float rstd = rsqrtf(var + 1e-5f);
            float y0 = d0 * rstd * lg0 + lb0;
            float y1 = d1 * rstd * lg1 + lb1;
            __stcg(&g_h[(size_t)cta * Dd + tid],       y0);
            __stcg(&g_h[(size_t)cta * Dd + tid + 256], y1);
            if (t > 0) {
                g_H[((size_t)(t - 1) * Bn + cta) * Dd + tid]       = y0;
                g_H[((size_t)(t - 1) * Bn + cta) * Dd + tid + 256] = y1;
            }
            __syncthreads();
        }
        grid_barrier(target);
    }

    // recurrence done -> join the FC tile pool
    fc_tiles(sbuf, fcW, fcb, out);
#undef GXLOAD
}

// ---------------- Gx GEMM, bf16x3:  C = A(MxK) * B(NxK)^T + b1 + b2 ----------
__global__ void __launch_bounds__(256)
gemm_gx_bf16(const float* __restrict__ A, int M, int lda,
             const float* __restrict__ Bm, int N, int ldb, int K,
             const float* __restrict__ bias1, const float* __restrict__ bias2,
             float* __restrict__ C, int ldc)
{
    __shared__ uint2 Ash[8][132];
    __shared__ uint2 Bsh[8][68];

    const int tid  = threadIdx.x;
    const int lane = tid & 31;
    const int warp = tid >> 5;
    const int wn = warp & 1, wm = warp >> 1;
    const int gid = lane >> 2, t4 = lane & 3;
    const int m0 = blockIdx.x * 128;
    const int n0 = blockIdx.y * 64;

    float acc[2][4][4];
#pragma unroll
    for (int i = 0; i < 2; i++)
#pragma unroll
        for (int j = 0; j < 4; j++)
#pragma unroll
            for (int q = 0; q < 4; q++) acc[i][j][q] = 0.f;

    float4 ra[2], rb;
    const int arow = tid >> 2,  acb = tid & 3;
    const int brow = (tid & 255) >> 2;
#define LOAD_T(K0)                                                           \
    {                                                                        \
        ra[0] = *(const float4*)(A + (size_t)(m0 + arow) * lda + (K0) + acb * 4);       \
        ra[1] = *(const float4*)(A + (size_t)(m0 + arow + 64) * lda + (K0) + acb * 4);  \
        rb    = *(const float4*)(Bm + (size_t)(n0 + brow) * ldb + (K0) + acb * 4);      \
    }

    LOAD_T(0)

    for (int k0 = 0; k0 < K; k0 += 16) {
#pragma unroll
        for (int i = 0; i < 2; i++) {
            unsigned h01 = bpack(ra[i].x, ra[i].y);
            unsigned h23 = bpack(ra[i].z, ra[i].w);
            unsigned l01 = bpack(ra[i].x - blo(h01), ra[i].y - bhi(h01));
            unsigned l23 = bpack(ra[i].z - blo(h23), ra[i].w - bhi(h23));
            Ash[acb * 2    ][arow + i * 64] = make_uint2(h01, l01);
            Ash[acb * 2 + 1][arow + i * 64] = make_uint2(h23, l23);
        }
        {
            unsigned h01 = bpack(rb.x, rb.y);
            unsigned h23 = bpack(rb.z, rb.w);
            unsigned l01 = bpack(rb.x - blo(h01), rb.y - bhi(h01));
            unsigned l23 = bpack(rb.z - blo(h23), rb.w - bhi(h23));
            Bsh[acb * 2    ][brow] = make_uint2(h01, l01);
            Bsh[acb * 2 + 1][brow] = make_uint2(h23, l23);
        }
        __syncthreads();

        if (k0 + 16 < K) LOAD_T(k0 + 16)

        uint2 a0[2], a1[2], a2[2], a3[2];
#pragma unroll
        for (int mf = 0; mf < 2; mf++) {
            int mm = wm * 32 + mf * 16 + gid;
            a0[mf] = Ash[t4    ][mm];
            a1[mf] = Ash[t4    ][mm + 8];
            a2[mf] = Ash[t4 + 4][mm];
            a3[mf] = Ash[t4 + 4][mm + 8];
        }
#pragma unroll
        for (int nf = 0; nf < 4; nf++) {
            int nn = wn * 32 + nf * 8 + gid;
            uint2 b0 = Bsh[t4    ][nn];
            uint2 b1 = Bsh[t4 + 4][nn];
#pragma unroll
            for (int mf = 0; mf < 2; mf++) {
                mma_bf16(acc[mf][nf], a0[mf].x, a1[mf].x, a2[mf].x, a3[mf].x, b0.x, b1.x);
                mma_bf16(acc[mf][nf], a0[mf].y, a1[mf].y, a2[mf].y, a3[mf].y, b0.x, b1.x);
                mma_bf16(acc[mf][nf], a0[mf].x, a1[mf].x, a2[mf].x, a3[mf].x, b0.y, b1.y);
            }
        }
        __syncthreads();
    }

#pragma unroll
    for (int mf = 0; mf < 2; mf++)
#pragma unroll
        for (int nf = 0; nf < 4; nf++) {
            int r0 = m0 + wm * 32 + mf * 16 + gid;
            int c0 = n0 + wn * 32 + nf * 8 + 2 * t4;
#pragma unroll
            for (int q = 0; q < 4; q++) {
                int r = r0 + ((q >= 2) ? 8 : 0);
                int c = c0 + (q & 1);
                C[(size_t)r * ldc + c] = acc[mf][nf][q] + bias1[c] + bias2[c];
            }
        }
#undef LOAD_T
}

// ---------------- in-place log_softmax, rows of 10000 ------------------------
__global__ void k_lsm(float* __restrict__ out) {
    __shared__ float row[Vv];
    __shared__ float red[8];
    float* p = out + (size_t)blockIdx.x * Vv;
    int tid = threadIdx.x;

    float mx = -1e30f;
    float4*       r4 = (float4*)row;
    const float4* p4 = (const float4*)p;
    for (int i = tid; i < Vv / 4; i += 256) {
        float4 v = p4[i];
        r4[i] = v;
        mx = fmaxf(mx, fmaxf(fmaxf(v.x, v.y), fmaxf(v.z, v.w)));
    }
#pragma unroll
    for (int o = 16; o > 0; o >>= 1) mx = fmaxf(mx, __shfl_xor_sync(0xffffffffu, mx, o));
    if ((tid & 31) == 0) red[tid >> 5] = mx;
    __syncthreads();
    mx = red[0];
#pragma unroll
    for (int i = 1; i < 8; i++) mx = fmaxf(mx, red[i]);

    float s = 0.f;
    for (int i = tid; i < Vv; i += 256) s += expf(row[i] - mx);
#pragma unroll
    for (int o = 16; o > 0; o >>= 1) s += __shfl_xor_sync(0xffffffffu, s, o);
    __syncthreads();
    if ((tid & 31) == 0) red[tid >> 5] = s;
    __syncthreads();
    s = red[0] + red[1] + red[2] + red[3] + red[4] + red[5] + red[6] + red[7];
    float lse = mx + logf(s);

    for (int i = tid; i < Vv; i += 256) p[i] = row[i] - lse;
}

// ---------------- host launcher ----------------------------------------------
extern "C" void kernel_launch(void* const* d_in, const int* in_sizes, int n_in,
                              void* d_out, int out_size) {
    const float* features = (const float*)d_in[0];
    const void*  caption  = d_in[1];
    const float* embW     = (const float*)d_in[2];
    const float* Wih      = (const float*)d_in[3];
    const float* Whh      = (const float*)d_in[4];
    const float* bih      = (const float*)d_in[5];
    const float* bhh      = (const float*)d_in[6];
    const float* lng      = (const float*)d_in[7];
    const float* lnb      = (const float*)d_in[8];
    const float* fcW      = (const float*)d_in[9];
    const float* fcb      = (const float*)d_in[10];
    float*       out      = (float*)d_out;

    float *pX, *pGx;
    cudaGetSymbolAddress((void**)&pX,  g_X);
    cudaGetSymbolAddress((void**)&pGx, g_Gx);

    cudaFuncSetAttribute(k_recurrence,
                         cudaFuncAttributeMaxDynamicSharedMemorySize, SMEM_REC);

    k_init<<<256, 256>>>();
    k_detect<<<1, 256>>>((const int*)caption);
    k_build_x<<<Tt * Bn, 128>>>(features, caption, embW);

    // Gx = X @ Wih^T + bih + bhh   (both layers, bf16x3)
    for (int l = 0; l < 2; l++)
        gemm_gx_bf16<<<dim3(33, 32), 256>>>(
            pX, Tt * Bn, Dd,
            Wih + (size_t)l * G4 * Dd, G4, Dd, Dd,
            bih + l * G4, bhh + l * G4,
            pGx + (size_t)l * Tt * Bn * G4, G4);

    // recurrence (128 CTAs) + overlapped FC (20 worker CTAs + joiners)
    k_recurrence<<<148, 256, SMEM_REC>>>(Whh, lng, lnb, fcW, fcb, out);

    k_lsm<<<Ll * Bn, 256>>>(out);
}

// round 10
// speedup vs baseline: 1.0591x; 1.0346x over previous
#include <cuda_runtime.h>
#include <math.h>
#include <stdint.h>

#define Bn   128
#define Dd   512
#define Tt   33
#define Ll   32
#define Vv   10000
#define G4   2048

// ---------------- static device scratch ------------------------------------
__device__ float    g_X  [Tt * Bn * Dd];        // per-step inputs
__device__ float    g_Gx [2 * Tt * Bn * G4];    // x-side gates (both layers)
__device__ float    g_H  [Ll * Bn * Dd];        // normalized h history
__device__ float    g_h  [Bn * Dd];             // carried h (normalized)
__device__ float    g_hm [Bn * Dd];             // h after layer 0
__device__ float    g_hr [Bn * Dd];             // h after layer 1 (pre-LN)
__device__ unsigned g_bar;                      // grid barrier counter
__device__ int      g_cap64;

// ---------------- utility kernels -------------------------------------------
__global__ void k_init() {
    int i = blockIdx.x * blockDim.x + threadIdx.x;
    if (i < Bn * Dd) g_h[i] = 0.f;
    if (i == 0) g_bar = 0u;
}

// caption int64 vs int32 detection (values < 10000 => int64 high words all 0)
__global__ void k_detect(const int* __restrict__ cap) {
    int any = 0;
    for (int i = threadIdx.x; i < 2048; i += blockDim.x)
        if (cap[2 * i + 1] != 0) any = 1;
    any = __syncthreads_or(any);
    if (threadIdx.x == 0) g_cap64 = any ? 0 : 1;
}

__global__ void k_build_x(const float* __restrict__ features,
                          const void*  __restrict__ cap,
                          const float* __restrict__ embW) {
    int blk = blockIdx.x;
    int t = blk >> 7;
    int b = blk & 127;
    const float* src;
    if (t == 0) {
        src = features + (size_t)b * Dd;
    } else {
        long long idx;
        if (g_cap64) idx = ((const long long*)cap)[b * Ll + (t - 1)];
        else         idx = (long long)((const int*)cap)[b * Ll + (t - 1)];
        src = embW + (size_t)idx * Dd;
    }
    float4*       dst = (float4*)(g_X + ((size_t)t * Bn + b) * Dd);
    const float4* s4  = (const float4*)src;
    dst[threadIdx.x] = s4[threadIdx.x];
}

// ---------------- tf32 helpers (FC path) -------------------------------------
__device__ __forceinline__ unsigned f2t(float x) {
    unsigned r;
    asm("cvt.rna.tf32.f32 %0, %1;" : "=r"(r) : "f"(x));
    return r;
}

__device__ __forceinline__ void mma_tf32(float* c, const unsigned* a, const unsigned* b) {
    asm volatile(
        "mma.sync.aligned.m16n8k8.row.col.f32.tf32.tf32.f32 "
        "{%0,%1,%2,%3}, {%4,%5,%6,%7}, {%8,%9}, {%0,%1,%2,%3};\n"
        : "+f"(c[0]), "+f"(c[1]), "+f"(c[2]), "+f"(c[3])
        : "r"(a[0]), "r"(a[1]), "r"(a[2]), "r"(a[3]), "r"(b[0]), "r"(b[1]));
}

// ---------------- bf16 helpers -------------------------------------------------
__device__ __forceinline__ unsigned bpack(float e0, float e1) {
    unsigned r;
    asm("cvt.rn.bf16x2.f32 %0, %1, %2;" : "=r"(r) : "f"(e1), "f"(e0));
    return r;
}
__device__ __forceinline__ float blo(unsigned p) { return __uint_as_float(p << 16); }
__device__ __forceinline__ float bhi(unsigned p) { return __uint_as_float(p & 0xffff0000u); }

__device__ __forceinline__ void mma_bf16(float* c,
                                         unsigned a0, unsigned a1, unsigned a2, unsigned a3,
                                         unsigned b0, unsigned b1) {
    asm volatile(
        "mma.sync.aligned.m16n8k16.row.col.f32.bf16.bf16.f32 "
        "{%0,%1,%2,%3}, {%4,%5,%6,%7}, {%8,%9}, {%0,%1,%2,%3};\n"
        : "+f"(c[0]), "+f"(c[1]), "+f"(c[2]), "+f"(c[3])
        : "r"(a0), "r"(a1), "r"(a2), "r"(a3), "r"(b0), "r"(b1));
}

// ---------------- fast activations (saturation-safe) -------------------------
__device__ __forceinline__ float fsig(float x) {
    float e = __expf(-x);
    return __fdividef(1.f, 1.f + e);
}
__device__ __forceinline__ float ftanh(float x) {
    float e = __expf(2.f * x);
    return 1.f - __fdividef(2.f, e + 1.f);
}

// ---------------- fence-free grid barrier ------------------------------------
__device__ __forceinline__ void grid_barrier(unsigned& target) {
    __syncthreads();
    if (threadIdx.x == 0) {
        target += gridDim.x;
        unsigned* bar = &g_bar;
        asm volatile("red.release.gpu.global.add.u32 [%0], 1;" :: "l"(bar) : "memory");
        unsigned v;
        do {
            asm volatile("ld.acquire.gpu.global.u32 %0, [%1];" : "=r"(v) : "l"(bar) : "memory");
        } while (v < target);
    }
    __syncthreads();
}

// ---------------- persistent recurrence kernel -------------------------------
// 128 CTAs x 512 threads = 2 batch-groups (64 rows) x 64 j-groups (8 cols).
// 16 warps = 4(M) x 4(N); warp tile 16x8 -> 4 warps/SMSP for latency hiding.
// Whh slice (both layers) pre-split to bf16 hi/lo pairs, resident in smem.
// smem layout (bytes):
//   Bsm  uint2[2*32][258]   0      .. 132096
//   Asm  uint2[128][66]     132096 .. 199680
//   Cs   float[64][36]      199680 .. 208896
//   csm  float[64][8]       208896 .. 210944
//   red  float[16]          210944 .. 211008
#define SMEM_REC 211008
__global__ void __launch_bounds__(512, 1)
k_recurrence(const float* __restrict__ Whh,
             const float* __restrict__ lng, const float* __restrict__ lnb) {
    extern __shared__ __align__(16) char sbuf[];
    uint2* Bsm       = (uint2*)sbuf;                      // [(l*32+row)*258 + kp]
    uint2 (*Asm)[66] = (uint2(*)[66])(sbuf + 132096);     // [kp][row]
    float (*Cs)[36]  = (float(*)[36])(sbuf + 199680);
    float (*csm)[8]  = (float(*)[8])(sbuf + 208896);
    float* red       = (float*)(sbuf + 210944);

    const int tid  = threadIdx.x;
    const int lane = tid & 31;
    const int warp = tid >> 5;
    const int gid  = lane >> 2, t4 = lane & 3;
    const int cta  = blockIdx.x;             // 0..127
    const int jcta = cta & 63;               // j-group: cols [jcta*8, jcta*8+8)
    const int bm0  = (cta >> 6) * 64;        // batch-group base row
    const int wm   = warp >> 2, wn = warp & 3;  // 4x4 warps, warp tile 16x8
    unsigned target = 0;

    // ---- one-time: Whh slice (both layers) -> bf16 hi/lo pairs in smem ----
    for (int idx = tid; idx < 2 * 32 * 256; idx += 512) {
        int l  = idx >> 13;
        int rm = idx & 8191;
        int rl = rm >> 8;
        int kp = rm & 255;
        int p  = jcta * 32 + rl;
        int orig = ((p & 3) << 9) | (p >> 2);
        float2 v = *(const float2*)(Whh + ((size_t)l * G4 + orig) * Dd + kp * 2);
        unsigned h  = bpack(v.x, v.y);
        unsigned lo = bpack(v.x - blo(h), v.y - bhi(h));
        Bsm[(l * 32 + rl) * 258 + kp] = make_uint2(h, lo);
    }
    csm[tid >> 3][tid & 7] = 0.f;
    float lg = lng[tid], lb = lnb[tid];
    __syncthreads();

    for (int t = 0; t < Tt; t++) {
#pragma unroll 1
        for (int l = 0; l < 2; l++) {
            const float* A    = (l == 0) ? g_h : g_hm;
            const float* gx   = g_Gx + ((size_t)l * Tt + t) * Bn * G4;
            float*       hout = (l == 0) ? g_hm : g_hr;
            const int    l32  = l * 32;

            // ---- prefetch gx gate values for the cell epilogue (4 LDG) ----
            float gpre[4];
            {
                int b = bm0 + (tid >> 3);
                int j = jcta * 8 + (tid & 7);
                gpre[0] = __ldg(&gx[b * G4 + j]);
                gpre[1] = __ldg(&gx[b * G4 + 512 + j]);
                gpre[2] = __ldg(&gx[b * G4 + 1024 + j]);
                gpre[3] = __ldg(&gx[b * G4 + 1536 + j]);
            }

            float accA[4], accB[4];
#pragma unroll
            for (int q = 0; q < 4; q++) { accA[q] = 0.f; accB[q] = 0.f; }

#pragma unroll 1
            for (int half = 0; half < 2; half++) {
                // ---- stage A half: 64 rows x 256 k -> bf16 hi/lo pairs ----
                const float* Ag = A + (size_t)bm0 * Dd + half * 256;
                const int c4 = tid & 63;
#pragma unroll
                for (int r = 0; r < 8; r++) {
                    int row = (tid >> 6) + r * 8;
                    float4 v = __ldcg((const float4*)(Ag + (size_t)row * Dd + c4 * 4));
                    unsigned h01 = bpack(v.x, v.y);
                    unsigned h23 = bpack(v.z, v.w);
                    unsigned l01 = bpack(v.x - blo(h01), v.y - bhi(h01));
                    unsigned l23 = bpack(v.z - blo(h23), v.w - bhi(h23));
                    Asm[c4 * 2    ][row] = make_uint2(h01, l01);
                    Asm[c4 * 2 + 1][row] = make_uint2(h23, l23);
                }
                __syncthreads();

                const int mm  = wm * 16 + gid;
                const int nn  = wn * 8 + gid;
                const int kpb = half * 128;
#pragma unroll
                for (int i = 0; i < 16; i++) {
                    uint2 a0 = Asm[i * 8 + t4    ][mm];
                    uint2 a1 = Asm[i * 8 + t4    ][mm + 8];
                    uint2 a2 = Asm[i * 8 + t4 + 4][mm];
                    uint2 a3 = Asm[i * 8 + t4 + 4][mm + 8];
                    uint2 b0 = Bsm[(l32 + nn) * 258 + kpb + i * 8 + t4    ];
                    uint2 b1 = Bsm[(l32 + nn) * 258 + kpb + i * 8 + t4 + 4];
                    mma_bf16(accA, a0.x, a1.x, a2.x, a3.x, b0.x, b1.x);  // hi.hi
                    mma_bf16(accB, a0.y, a1.y, a2.y, a3.y, b0.x, b1.x);  // lo.hi
                    mma_bf16(accB, a0.x, a1.x, a2.x, a3.x, b0.y, b1.y);  // hi.lo
                }
                __syncthreads();
            }
            // accumulators -> Cs
            {
                int r0 = wm * 16 + gid;
                int c0 = wn * 8 + 2 * t4;
                Cs[r0    ][c0    ] = accA[0] + accB[0];
                Cs[r0    ][c0 + 1] = accA[1] + accB[1];
                Cs[r0 + 8][c0    ] = accA[2] + accB[2];
                Cs[r0 + 8][c0 + 1] = accA[3] + accB[3];
            }
            __syncthreads();
            // LSTM cell: 64x8 = 512 elements, 1 per thread (gx preloaded)
            {
                int brow = tid >> 3, jj = tid & 7;
                int b    = bm0 + brow;
                int j    = jcta * 8 + jj;
                float gi = Cs[brow][jj * 4 + 0] + gpre[0];
                float gf = Cs[brow][jj * 4 + 1] + gpre[1];
                float gg = Cs[brow][jj * 4 + 2] + gpre[2];
                float go = Cs[brow][jj * 4 + 3] + gpre[3];
                float ii = fsig(gi);
                float ff = fsig(gf);
                float gt = ftanh(gg);
                float oo = fsig(go);
                float cn = ff * csm[brow][jj] + ii * gt;
                csm[brow][jj] = cn;
                __stcg(&hout[(size_t)b * Dd + j], oo * ftanh(cn));
            }
            grid_barrier(target);
        }
        // ---- LayerNorm: CTA handles batch row b = cta (512 threads, 1 elem) --
        {
            const float* xr = g_hr + (size_t)cta * Dd;
            float v = __ldcg(&xr[tid]);
            float s = v;
#pragma unroll
            for (int o = 16; o > 0; o >>= 1) s += __shfl_xor_sync(0xffffffffu, s, o);
            if (lane == 0) red[warp] = s;
            __syncthreads();
            float mu = 0.f;
#pragma unroll
            for (int i = 0; i < 16; i++) mu += red[i];
            mu *= (1.f / 512.f);
            __syncthreads();
            float d = v - mu;
            float vv = d * d;
#pragma unroll
            for (int o = 16; o > 0; o >>= 1) vv += __shfl_xor_sync(0xffffffffu, vv, o);
            if (lane == 0) red[warp] = vv;
            __syncthreads();
            float var = 0.f;
#pragma unroll
            for (int i = 0; i < 16; i++) var += red[i];
            var *= (1.f / 512.f);
            float rstd = rsqrtf(var + 1e-5f);
            float y = d * rstd * lg + lb;
            __stcg(&g_h[(size_t)cta * Dd + tid], y);
            if (t > 0)
                g_H[((size_t)(t - 1) * Bn + cta) * Dd + tid] = y;
            __syncthreads();
        }
        grid_barrier(target);
    }
}

// ---------------- Gx GEMM, bf16x3:  C = A(MxK) * B(NxK)^T + b1 + b2 ----------
__global__ void __launch_bounds__(256)
gemm_gx_bf16(const float* __restrict__ A, int M, int lda,
             const float* __restrict__ Bm, int N, int ldb, int K,
             const float* __restrict__ bias1, const float* __restrict__ bias2,
             float* __restrict__ C, int ldc)
{
    __shared__ uint2 Ash[8][132];
    __shared__ uint2 Bsh[8][68];

    const int tid  = threadIdx.x;
    const int lane = tid & 31;
    const int warp = tid >> 5;
    const int wn = warp & 1, wm = warp >> 1;
    const int gid = lane >> 2, t4 = lane & 3;
    const int m0 = blockIdx.x * 128;
    const int n0 = blockIdx.y * 64;

    float acc[2][4][4];
#pragma unroll
    for (int i = 0; i < 2; i++)
#pragma unroll
        for (int j = 0; j < 4; j++)
#pragma unroll
            for (int q = 0; q < 4; q++) acc[i][j][q] = 0.f;

    float4 ra[2], rb;
    const int arow = tid >> 2,  acb = tid & 3;
    const int brow = (tid & 255) >> 2;
#define LOAD_T(K0)                                                           \
    {                                                                        \
        ra[0] = *(const float4*)(A + (size_t)(m0 + arow) * lda + (K0) + acb * 4);       \
        ra[1] = *(const float4*)(A + (size_t)(m0 + arow + 64) * lda + (K0) + acb * 4);  \
        rb    = *(const float4*)(Bm + (size_t)(n0 + brow) * ldb + (K0) + acb * 4);      \
    }

    LOAD_T(0)

    for (int k0 = 0; k0 < K; k0 += 16) {
#pragma unroll
        for (int i = 0; i < 2; i++) {
            unsigned h01 = bpack(ra[i].x, ra[i].y);
            unsigned h23 = bpack(ra[i].z, ra[i].w);
            unsigned l01 = bpack(ra[i].x - blo(h01), ra[i].y - bhi(h01));
            unsigned l23 = bpack(ra[i].z - blo(h23), ra[i].w - bhi(h23));
            Ash[acb * 2    ][arow + i * 64] = make_uint2(h01, l01);
            Ash[acb * 2 + 1][arow + i * 64] = make_uint2(h23, l23);
        }
        {
            unsigned h01 = bpack(rb.x, rb.y);
            unsigned h23 = bpack(rb.z, rb.w);
            unsigned l01 = bpack(rb.x - blo(h01), rb.y - bhi(h01));
            unsigned l23 = bpack(rb.z - blo(h23), rb.w - bhi(h23));
            Bsh[acb * 2    ][brow] = make_uint2(h01, l01);
            Bsh[acb * 2 + 1][brow] = make_uint2(h23, l23);
        }
        __syncthreads();

        if (k0 + 16 < K) LOAD_T(k0 + 16)

        uint2 a0[2], a1[2], a2[2], a3[2];
#pragma unroll
        for (int mf = 0; mf < 2; mf++) {
            int mm = wm * 32 + mf * 16 + gid;
            a0[mf] = Ash[t4    ][mm];
            a1[mf] = Ash[t4    ][mm + 8];
            a2[mf] = Ash[t4 + 4][mm];
            a3[mf] = Ash[t4 + 4][mm + 8];
        }
#pragma unroll
        for (int nf = 0; nf < 4; nf++) {
            int nn = wn * 32 + nf * 8 + gid;
            uint2 b0 = Bsh[t4    ][nn];
            uint2 b1 = Bsh[t4 + 4][nn];
#pragma unroll
            for (int mf = 0; mf < 2; mf++) {
                mma_bf16(acc[mf][nf], a0[mf].x, a1[mf].x, a2[mf].x, a3[mf].x, b0.x, b1.x);
                mma_bf16(acc[mf][nf], a0[mf].y, a1[mf].y, a2[mf].y, a3[mf].y, b0.x, b1.x);
                mma_bf16(acc[mf][nf], a0[mf].x, a1[mf].x, a2[mf].x, a3[mf].x, b0.y, b1.y);
            }
        }
        __syncthreads();
    }

#pragma unroll
    for (int mf = 0; mf < 2; mf++)
#pragma unroll
        for (int nf = 0; nf < 4; nf++) {
            int r0 = m0 + wm * 32 + mf * 16 + gid;
            int c0 = n0 + wn * 32 + nf * 8 + 2 * t4;
#pragma unroll
            for (int q = 0; q < 4; q++) {
                int r = r0 + ((q >= 2) ? 8 : 0);
                int c = c0 + (q & 1);
                C[(size_t)r * ldc + c] = acc[mf][nf][q] + bias1[c] + bias2[c];
            }
        }
#undef LOAD_T
}

// ---------------- FC GEMM (tf32 single): permuted store ----------------------
template<int BM, int BN, int WM, int WN>
__global__ void __launch_bounds__(WM * WN * 32)
gemm_fc(const float* __restrict__ A, int M, int lda,
        const float* __restrict__ Bm, int N, int ldb, int K,
        const float* __restrict__ bias1,
        float* __restrict__ C, int ldc)
{
    constexpr int THREADS = WM * WN * 32;
    constexpr int PAD = 4;
    constexpr int MF = 2, NF = 4;

    __shared__ unsigned Ash[16][BM + PAD];
    __shared__ unsigned Bsh[16][BN + PAD];

    const int tid  = threadIdx.x;
    const int lane = tid & 31;
    const int warp = tid >> 5;
    const int wn = warp % WN, wm = warp / WN;
    const int gid = lane >> 2, t4 = lane & 3;
    const int m0 = blockIdx.x * BM;
    const int n0 = blockIdx.y * BN;

    float acc[MF][NF][4];
#pragma unroll
    for (int i = 0; i < MF; i++)
#pragma unroll
        for (int j = 0; j < NF; j++)
#pragma unroll
            for (int q = 0; q < 4; q++) acc[i][j][q] = 0.f;

    constexpr int LA = (BM * 16) / (THREADS * 4);
    constexpr int LB = (BN * 16) / (THREADS * 4);

    float4 ra[LA], rb[LB];

#define LOAD_T(K0)                                                          \
    {                                                                       \
        _Pragma("unroll")                                                   \
        for (int i = 0; i < LA; i++) {                                      \
            int f4 = tid + i * THREADS;                                     \
            int row = f4 >> 2, cb = f4 & 3;                                 \
            int gm = m0 + row;                                              \
            ra[i] = make_float4(0.f, 0.f, 0.f, 0.f);                        \
            if (gm < M) ra[i] = *(const float4*)(A + (size_t)gm * lda + (K0) + cb * 4); \
        }                                                                   \
        _Pragma("unroll")                                                   \
        for (int i = 0; i < LB; i++) {                                      \
            int f4 = tid + i * THREADS;                                     \
            int row = f4 >> 2, cb = f4 & 3;                                 \
            int grow = n0 + row;                                            \
            rb[i] = make_float4(0.f, 0.f, 0.f, 0.f);                        \
            if (grow < N) rb[i] = *(const float4*)(Bm + (size_t)grow * ldb + (K0) + cb * 4); \
        }                                                                   \
    }

    LOAD_T(0)

    for (int k0 = 0; k0 < K; k0 += 16) {
#pragma unroll
        for (int i = 0; i < LA; i++) {
            int f4 = tid + i * THREADS;
            int row = f4 >> 2, cb = f4 & 3;
            Ash[cb * 4 + 0][row] = f2t(ra[i].x);
            Ash[cb * 4 + 1][row] = f2t(ra[i].y);
            Ash[cb * 4 + 2][row] = f2t(ra[i].z);
            Ash[cb * 4 + 3][row] = f2t(ra[i].w);
        }
#pragma unroll
        for (int i = 0; i < LB; i++) {
            int f4 = tid + i * THREADS;
            int row = f4 >> 2, cb = f4 & 3;
            Bsh[cb * 4 + 0][row] = f2t(rb[i].x);
            Bsh[cb * 4 + 1][row] = f2t(rb[i].y);
            Bsh[cb * 4 + 2][row] = f2t(rb[i].z);
            Bsh[cb * 4 + 3][row] = f2t(rb[i].w);
        }
        __syncthreads();

        if (k0 + 16 < K) LOAD_T(k0 + 16)

#pragma unroll
        for (int ks = 0; ks < 2; ks++) {
            const int kb = ks * 8;
            unsigned ah[MF][4], bh[NF][2];
#pragma unroll
            for (int mf = 0; mf < MF; mf++) {
                int mm = wm * 32 + mf * 16 + gid;
                ah[mf][0] = Ash[kb + t4    ][mm];
                ah[mf][1] = Ash[kb + t4    ][mm + 8];
                ah[mf][2] = Ash[kb + t4 + 4][mm];
                ah[mf][3] = Ash[kb + t4 + 4][mm + 8];
            }
#pragma unroll
            for (int nf = 0; nf < NF; nf++) {
                int nn = wn * 32 + nf * 8 + gid;
                bh[nf][0] = Bsh[kb + t4    ][nn];
                bh[nf][1] = Bsh[kb + t4 + 4][nn];
            }
#pragma unroll
            for (int mf = 0; mf < MF; mf++)
#pragma unroll
                for (int nf = 0; nf < NF; nf++)
                    mma_tf32(acc[mf][nf], ah[mf], bh[nf]);
        }
        __syncthreads();
    }

#pragma unroll
    for (int mf = 0; mf < MF; mf++)
#pragma unroll
        for (int nf = 0; nf < NF; nf++) {
            int r0 = m0 + wm * 32 + mf * 16 + gid;
            int c0 = n0 + wn * 32 + nf * 8 + 2 * t4;
#pragma unroll
            for (int q = 0; q < 4; q++) {
                int r = r0 + ((q >= 2) ? 8 : 0);
                int c = c0 + (q & 1);
                if (r < M && c < N) {
                    int orow = (r & 127) * Ll + (r >> 7);
                    C[(size_t)orow * ldc + c] = acc[mf][nf][q] + bias1[c];
                }
            }
        }
#undef LOAD_T
}

// ---------------- in-place log_softmax, rows of 10000 ------------------------
__global__ void k_lsm(float* __restrict__ out) {
    __shared__ float row[Vv];
    __shared__ float red[8];
    float* p = out + (size_t)blockIdx.x * Vv;
    int tid = threadIdx.x;

    float mx = -1e30f;
    float4*       r4 = (float4*)row;
    const float4* p4 = (const float4*)p;
    for (int i = tid; i < Vv / 4; i += 256) {
        float4 v = p4[i];
        r4[i] = v;
        mx = fmaxf(mx, fmaxf(fmaxf(v.x, v.y), fmaxf(v.z, v.w)));
    }
#pragma unroll
    for (int o = 16; o > 0; o >>= 1) mx = fmaxf(mx, __shfl_xor_sync(0xffffffffu, mx, o));
    if ((tid & 31) == 0) red[tid >> 5] = mx;
    __syncthreads();
    mx = red[0];
#pragma unroll
    for (int i = 1; i < 8; i++) mx = fmaxf(mx, red[i]);

    float s = 0.f;
    for (int i = tid; i < Vv; i += 256) s += expf(row[i] - mx);
#pragma unroll
    for (int o = 16; o > 0; o >>= 1) s += __shfl_xor_sync(0xffffffffu, s, o);
    __syncthreads();
    if ((tid & 31) == 0) red[tid >> 5] = s;
    __syncthreads();
    s = red[0] + red[1] + red[2] + red[3] + red[4] + red[5] + red[6] + red[7];
    float lse = mx + logf(s);

    for (int i = tid; i < Vv; i += 256) p[i] = row[i] - lse;
}

// ---------------- host launcher ----------------------------------------------
extern "C" void kernel_launch(void* const* d_in, const int* in_sizes, int n_in,
                              void* d_out, int out_size) {
    const float* features = (const float*)d_in[0];
    const void*  caption  = d_in[1];
    const float* embW     = (const float*)d_in[2];
    const float* Wih      = (const float*)d_in[3];
    const float* Whh      = (const float*)d_in[4];
    const float* bih      = (const float*)d_in[5];
    const float* bhh      = (const float*)d_in[6];
    const float* lng      = (const float*)d_in[7];
    const float* lnb      = (const float*)d_in[8];
    const float* fcW      = (const float*)d_in[9];
    const float* fcb      = (const float*)d_in[10];
    float*       out      = (float*)d_out;

    float *pX, *pGx, *pH;
    cudaGetSymbolAddress((void**)&pX,  g_X);
    cudaGetSymbolAddress((void**)&pGx, g_Gx);
    cudaGetSymbolAddress((void**)&pH,  g_H);

    cudaFuncSetAttribute(k_recurrence,
                         cudaFuncAttributeMaxDynamicSharedMemorySize, SMEM_REC);

    k_init<<<256, 256>>>();
    k_detect<<<1, 256>>>((const int*)caption);
    k_build_x<<<Tt * Bn, 128>>>(features, caption, embW);

    // Gx = X @ Wih^T + bih + bhh   (both layers, bf16x3)
    for (int l = 0; l < 2; l++)
        gemm_gx_bf16<<<dim3(33, 32), 256>>>(
            pX, Tt * Bn, Dd,
            Wih + (size_t)l * G4 * Dd, G4, Dd, Dd,
            bih + l * G4, bhh + l * G4,
            pGx + (size_t)l * Tt * Bn * G4, G4);

    // full 33-step recurrence in ONE persistent kernel (single wave)
    k_recurrence<<<128, 512, SMEM_REC>>>(Whh, lng, lnb);

    // FC: logits = H @ fcW^T + fcb  (single tf32, permuted store)
    gemm_fc<128, 64, 4, 2><<<dim3(32, 157), 256>>>(
        pH, Ll * Bn, Dd, fcW, Vv, Dd, Dd,
        fcb, out, Vv);

    k_lsm<<<Ll * Bn, 256>>>(out);
}

// round 11
// speedup vs baseline: 1.1707x; 1.1054x over previous
#include <cuda_runtime.h>
#include <math.h>
#include <stdint.h>

#define Bn   128
#define Dd   512
#define Tt   33
#define Ll   32
#define Vv   10000
#define G4   2048

// ---------------- static device scratch ------------------------------------
__device__ float    g_X  [Tt * Bn * Dd];        // per-step inputs
__device__ float    g_Gx [2 * Tt * Bn * G4];    // x-side gates (both layers)
__device__ float    g_H  [Ll * Bn * Dd];        // normalized h history
__device__ float    g_h  [Bn * Dd];             // carried h (normalized)
__device__ float    g_hm [Bn * Dd];             // h after layer 0
__device__ float    g_hr [Bn * Dd];             // h after layer 1 (pre-LN)
__device__ __align__(128) unsigned g_bar0;      // group-0 barrier counter
__device__ __align__(128) unsigned g_bar1;      // group-1 barrier counter (own line)
__device__ int      g_cap64;

// ---------------- utility kernels -------------------------------------------
__global__ void k_init() {
    int i = blockIdx.x * blockDim.x + threadIdx.x;
    if (i < Bn * Dd) g_h[i] = 0.f;
    if (i == 0) { g_bar0 = 0u; g_bar1 = 0u; }
}

// caption int64 vs int32 detection (values < 10000 => int64 high words all 0)
__global__ void k_detect(const int* __restrict__ cap) {
    int any = 0;
    for (int i = threadIdx.x; i < 2048; i += blockDim.x)
        if (cap[2 * i + 1] != 0) any = 1;
    any = __syncthreads_or(any);
    if (threadIdx.x == 0) g_cap64 = any ? 0 : 1;
}

__global__ void k_build_x(const float* __restrict__ features,
                          const void*  __restrict__ cap,
                          const float* __restrict__ embW) {
    int blk = blockIdx.x;
    int t = blk >> 7;
    int b = blk & 127;
    const float* src;
    if (t == 0) {
        src = features + (size_t)b * Dd;
    } else {
        long long idx;
        if (g_cap64) idx = ((const long long*)cap)[b * Ll + (t - 1)];
        else         idx = (long long)((const int*)cap)[b * Ll + (t - 1)];
        src = embW + (size_t)idx * Dd;
    }
    float4*       dst = (float4*)(g_X + ((size_t)t * Bn + b) * Dd);
    const float4* s4  = (const float4*)src;
    dst[threadIdx.x] = s4[threadIdx.x];
}

// ---------------- tf32 helpers (FC path) -------------------------------------
__device__ __forceinline__ unsigned f2t(float x) {
    unsigned r;
    asm("cvt.rna.tf32.f32 %0, %1;" : "=r"(r) : "f"(x));
    return r;
}

__device__ __forceinline__ void mma_tf32(float* c, const unsigned* a, const unsigned* b) {
    asm volatile(
        "mma.sync.aligned.m16n8k8.row.col.f32.tf32.tf32.f32 "
        "{%0,%1,%2,%3}, {%4,%5,%6,%7}, {%8,%9}, {%0,%1,%2,%3};\n"
        : "+f"(c[0]), "+f"(c[1]), "+f"(c[2]), "+f"(c[3])
        : "r"(a[0]), "r"(a[1]), "r"(a[2]), "r"(a[3]), "r"(b[0]), "r"(b[1]));
}

// ---------------- bf16 helpers -------------------------------------------------
// pack: e0 -> low half, e1 -> high half
__device__ __forceinline__ unsigned bpack(float e0, float e1) {
    unsigned r;
    asm("cvt.rn.bf16x2.f32 %0, %1, %2;" : "=r"(r) : "f"(e1), "f"(e0));
    return r;
}
__device__ __forceinline__ float blo(unsigned p) { return __uint_as_float(p << 16); }
__device__ __forceinline__ float bhi(unsigned p) { return __uint_as_float(p & 0xffff0000u); }

__device__ __forceinline__ void mma_bf16(float* c,
                                         unsigned a0, unsigned a1, unsigned a2, unsigned a3,
                                         unsigned b0, unsigned b1) {
    asm volatile(
        "mma.sync.aligned.m16n8k16.row.col.f32.bf16.bf16.f32 "
        "{%0,%1,%2,%3}, {%4,%5,%6,%7}, {%8,%9}, {%0,%1,%2,%3};\n"
        : "+f"(c[0]), "+f"(c[1]), "+f"(c[2]), "+f"(c[3])
        : "r"(a0), "r"(a1), "r"(a2), "r"(a3), "r"(b0), "r"(b1));
}

// ---------------- fast activations (saturation-safe) -------------------------
__device__ __forceinline__ float fsig(float x) {
    float e = __expf(-x);
    return __fdividef(1.f, 1.f + e);
}
__device__ __forceinline__ float ftanh(float x) {
    float e = __expf(2.f * x);
    return 1.f - __fdividef(2.f, e + 1.f);
}

// ---------------- fence-free per-group grid barrier (64 arrivals) ------------
__device__ __forceinline__ void grid_barrier(unsigned* bar, unsigned& target) {
    __syncthreads();
    if (threadIdx.x == 0) {
        target += 64u;
        asm volatile("red.release.gpu.global.add.u32 [%0], 1;" :: "l"(bar) : "memory");
        unsigned v;
        do {
            asm volatile("ld.acquire.gpu.global.u32 %0, [%1];" : "=r"(v) : "l"(bar) : "memory");
        } while (v < target);
    }
    __syncthreads();
}

// ---------------- persistent recurrence kernel -------------------------------
// 128 CTAs x 256 threads = 2 independent batch-groups (64 rows) x 64 j-groups.
// Whh slice (both layers) pre-split to bf16 hi/lo pairs, resident in smem.
// smem layout (bytes):
//   Bsm  uint2[2*32][258]   0      .. 132096
//   Asm  uint2[128][66]     132096 .. 199680
//   Cs   float[64][36]      199680 .. 208896
//   csm  float[64][8]       208896 .. 210944
//   red  float[8]           210944 .. 210976
#define SMEM_REC 210976
__global__ void __launch_bounds__(256, 1)
k_recurrence(const float* __restrict__ Whh,
             const float* __restrict__ lng, const float* __restrict__ lnb) {
    extern __shared__ __align__(16) char sbuf[];
    uint2* Bsm       = (uint2*)sbuf;                      // [(l*32+row)*258 + kp]
    uint2 (*Asm)[66] = (uint2(*)[66])(sbuf + 132096);     // [kp][row]
    float (*Cs)[36]  = (float(*)[36])(sbuf + 199680);
    float (*csm)[8]  = (float(*)[8])(sbuf + 208896);
    float* red       = (float*)(sbuf + 210944);

    const int tid  = threadIdx.x;
    const int lane = tid & 31;
    const int warp = tid >> 5;
    const int gid  = lane >> 2, t4 = lane & 3;
    const int cta  = blockIdx.x;             // 0..127
    const int jcta = cta & 63;               // j-group: cols [jcta*8, jcta*8+8)
    const int grp  = cta >> 6;               // batch group 0/1
    const int bm0  = grp * 64;               // batch-group base row
    const int wm   = warp >> 1, wn = warp & 1;  // 4x2 warps, warp tile 16x16
    unsigned* mybar = grp ? &g_bar1 : &g_bar0;
    unsigned target = 0;

    // ---- one-time: load + bf16-split this CTA's Whh slice (both layers) ----
    for (int idx = tid; idx < 2 * 32 * 256; idx += 256) {
        int l  = idx >> 13;
        int rm = idx & 8191;
        int rl = rm >> 8;                    // local row 0..31
        int kp = rm & 255;                   // k-pair 0..255
        int p  = jcta * 32 + rl;
        int orig = ((p & 3) << 9) | (p >> 2);
        float2 v = *(const float2*)(Whh + ((size_t)l * G4 + orig) * Dd + kp * 2);
        unsigned h = bpack(v.x, v.y);
        unsigned lo = bpack(v.x - blo(h), v.y - bhi(h));
        Bsm[(l * 32 + rl) * 258 + kp] = make_uint2(h, lo);
    }
    for (int i = tid; i < 64 * 8; i += 256) csm[i >> 3][i & 7] = 0.f;
    float lg0 = lng[tid], lg1 = lng[tid + 256];
    float lb0 = lnb[tid], lb1 = lnb[tid + 256];
    __syncthreads();

    float gpre[2][4];
#define GXLOAD(TT, LL)                                                    \
    {                                                                     \
        const float* gxp = g_Gx + ((size_t)(LL) * Tt + (TT)) * Bn * G4;   \
        _Pragma("unroll")                                                 \
        for (int it = 0; it < 2; it++) {                                  \
            int x = tid + it * 256;                                       \
            int b = bm0 + (x >> 3);                                       \
            int j = jcta * 8 + (x & 7);                                   \
            gpre[it][0] = __ldg(&gxp[b * G4 + j]);                        \
            gpre[it][1] = __ldg(&gxp[b * G4 + 512 + j]);                  \
            gpre[it][2] = __ldg(&gxp[b * G4 + 1024 + j]);                 \
            gpre[it][3] = __ldg(&gxp[b * G4 + 1536 + j]);                 \
        }                                                                 \
    }

    GXLOAD(0, 0)

    for (int t = 0; t < Tt; t++) {
#pragma unroll 1
        for (int l = 0; l < 2; l++) {
            const float* A    = (l == 0) ? g_h : g_hm;
            float*       hout = (l == 0) ? g_hm : g_hr;
            const int    l32  = l * 32;

            float accA[2][4], accB[2][4];
#pragma unroll
            for (int n = 0; n < 2; n++)
#pragma unroll
                for (int q = 0; q < 4; q++) { accA[n][q] = 0.f; accB[n][q] = 0.f; }

#pragma unroll 1
            for (int half = 0; half < 2; half++) {
                // ---- stage A half: 64 rows x 256 k -> bf16 hi/lo pairs ----
                const float* Ag = A + (size_t)bm0 * Dd + half * 256;
#pragma unroll
                for (int r = 0; r < 16; r++) {
                    int idx = tid + r * 256;
                    int row = idx >> 6, c4 = idx & 63;
                    float4 v = __ldcg((const float4*)(Ag + (size_t)row * Dd + c4 * 4));
                    unsigned h01 = bpack(v.x, v.y);
                    unsigned h23 = bpack(v.z, v.w);
                    unsigned l01 = bpack(v.x - blo(h01), v.y - bhi(h01));
                    unsigned l23 = bpack(v.z - blo(h23), v.w - bhi(h23));
                    Asm[c4 * 2    ][row] = make_uint2(h01, l01);
                    Asm[c4 * 2 + 1][row] = make_uint2(h23, l23);
                }
                __syncthreads();

                const int mm = wm * 16 + gid;
                const int kpb = half * 128;
#pragma unroll
                for (int i = 0; i < 16; i++) {
                    uint2 a0 = Asm[i * 8 + t4    ][mm];
                    uint2 a1 = Asm[i * 8 + t4    ][mm + 8];
                    uint2 a2 = Asm[i * 8 + t4 + 4][mm];
                    uint2 a3 = Asm[i * 8 + t4 + 4][mm + 8];
#pragma unroll
                    for (int nf = 0; nf < 2; nf++) {
                        int nn = wn * 16 + nf * 8 + gid;
                        uint2 b0 = Bsm[(l32 + nn) * 258 + kpb + i * 8 + t4    ];
                        uint2 b1 = Bsm[(l32 + nn) * 258 + kpb + i * 8 + t4 + 4];
                        mma_bf16(accA[nf], a0.x, a1.x, a2.x, a3.x, b0.x, b1.x);  // hi.hi
                        mma_bf16(accB[nf], a0.y, a1.y, a2.y, a3.y, b0.x, b1.x);  // lo.hi
                        mma_bf16(accB[nf], a0.x, a1.x, a2.x, a3.x, b0.y, b1.y);  // hi.lo
                    }
                }
                __syncthreads();
            }
            // accumulators -> Cs
#pragma unroll
            for (int nf = 0; nf < 2; nf++) {
                int r0 = wm * 16 + gid;
                int c0 = wn * 16 + nf * 8 + 2 * t4;
                Cs[r0    ][c0    ] = accA[nf][0] + accB[nf][0];
                Cs[r0    ][c0 + 1] = accA[nf][1] + accB[nf][1];
                Cs[r0 + 8][c0    ] = accA[nf][2] + accB[nf][2];
                Cs[r0 + 8][c0 + 1] = accA[nf][3] + accB[nf][3];
            }
            __syncthreads();
            // LSTM cell: 64x8 = 512 elements, 2 per thread (gx preloaded)
#pragma unroll
            for (int it = 0; it < 2; it++) {
                int x    = tid + it * 256;
                int brow = x >> 3, jj = x & 7;
                int b    = bm0 + brow;
                int j    = jcta * 8 + jj;
                float gi = Cs[brow][jj * 4 + 0] + gpre[it][0];
                float gf = Cs[brow][jj * 4 + 1] + gpre[it][1];
                float gg = Cs[brow][jj * 4 + 2] + gpre[it][2];
                float go = Cs[brow][jj * 4 + 3] + gpre[it][3];
                float ii = fsig(gi);
                float ff = fsig(gf);
                float gt = ftanh(gg);
                float oo = fsig(go);
                float cn = ff * csm[brow][jj] + ii * gt;
                csm[brow][jj] = cn;
                __stcg(&hout[(size_t)b * Dd + j], oo * ftanh(cn));
            }
            // hoist next phase's gx loads across the barrier (static data)
            if (l == 0) { GXLOAD(t, 1) }
            else if (t + 1 < Tt) { GXLOAD(t + 1, 0) }
            grid_barrier(mybar, target);
        }
        // ---- LayerNorm: CTA handles batch row b = cta (256 threads, 2 elems) --
        {
            const float* xr = g_hr + (size_t)cta * Dd;
            float v0 = __ldcg(&xr[tid]), v1 = __ldcg(&xr[tid + 256]);
            float s = v0 + v1;
#pragma unroll
            for (int o = 16; o > 0; o >>= 1) s += __shfl_xor_sync(0xffffffffu, s, o);
            if (lane == 0) red[warp] = s;
            __syncthreads();
            float mu = (red[0] + red[1] + red[2] + red[3] +
                        red[4] + red[5] + red[6] + red[7]) * (1.f / 512.f);
            __syncthreads();
            float d0 = v0 - mu, d1 = v1 - mu;
            float vv = d0 * d0 + d1 * d1;
#pragma unroll
            for (int o = 16; o > 0; o >>= 1) vv += __shfl_xor_sync(0xffffffffu, vv, o);
            if (lane == 0) red[warp] = vv;
            __syncthreads();
            float var  = (red[0] + red[1] + red[2] + red[3] +
                          red[4] + red[5] + red[6] + red[7]) * (1.f / 512.f);
            float rstd = rsqrtf(var + 1e-5f);
            float y0 = d0 * rstd * lg0 + lb0;
            float y1 = d1 * rstd * lg1 + lb1;
            __stcg(&g_h[(size_t)cta * Dd + tid],       y0);
            __stcg(&g_h[(size_t)cta * Dd + tid + 256], y1);
            if (t > 0) {
                g_H[((size_t)(t - 1) * Bn + cta) * Dd + tid]       = y0;
                g_H[((size_t)(t - 1) * Bn + cta) * Dd + tid + 256] = y1;
            }
            __syncthreads();
        }
        grid_barrier(mybar, target);
    }
#undef GXLOAD
}

// ---------------- Gx GEMM, bf16x3:  C = A(MxK) * B(NxK)^T + b1 + b2 ----------
// BM=128, BN=64, 256 threads, warp tile 32x32, k-tile 16 (8 bf16 pairs).
__global__ void __launch_bounds__(256)
gemm_gx_bf16(const float* __restrict__ A, int M, int lda,
             const float* __restrict__ Bm, int N, int ldb, int K,
             const float* __restrict__ bias1, const float* __restrict__ bias2,
             float* __restrict__ C, int ldc)
{
    __shared__ uint2 Ash[8][132];
    __shared__ uint2 Bsh[8][68];

    const int tid  = threadIdx.x;
    const int lane = tid & 31;
    const int warp = tid >> 5;
    const int wn = warp & 1, wm = warp >> 1;   // 4x2 warps
    const int gid = lane >> 2, t4 = lane & 3;
    const int m0 = blockIdx.x * 128;
    const int n0 = blockIdx.y * 64;

    float acc[2][4][4];
#pragma unroll
    for (int i = 0; i < 2; i++)
#pragma unroll
        for (int j = 0; j < 4; j++)
#pragma unroll
            for (int q = 0; q < 4; q++) acc[i][j][q] = 0.f;

    float4 ra[2], rb;
    const int arow = tid >> 2,  acb = tid & 3;
    const int brow = (tid & 255) >> 2;
#define LOAD_T(K0)                                                           \
    {                                                                        \
        ra[0] = *(const float4*)(A + (size_t)(m0 + arow) * lda + (K0) + acb * 4);       \
        ra[1] = *(const float4*)(A + (size_t)(m0 + arow + 64) * lda + (K0) + acb * 4);  \
        rb    = *(const float4*)(Bm + (size_t)(n0 + brow) * ldb + (K0) + acb * 4);      \
    }

    LOAD_T(0)

    for (int k0 = 0; k0 < K; k0 += 16) {
#pragma unroll
        for (int i = 0; i < 2; i++) {
            unsigned h01 = bpack(ra[i].x, ra[i].y);
            unsigned h23 = bpack(ra[i].z, ra[i].w);
            unsigned l01 = bpack(ra[i].x - blo(h01), ra[i].y - bhi(h01));
            unsigned l23 = bpack(ra[i].z - blo(h23), ra[i].w - bhi(h23));
            Ash[acb * 2    ][arow + i * 64] = make_uint2(h01, l01);
            Ash[acb * 2 + 1][arow + i * 64] = make_uint2(h23, l23);
        }
        {
            unsigned h01 = bpack(rb.x, rb.y);
            unsigned h23 = bpack(rb.z, rb.w);
            unsigned l01 = bpack(rb.x - blo(h01), rb.y - bhi(h01));
            unsigned l23 = bpack(rb.z - blo(h23), rb.w - bhi(h23));
            Bsh[acb * 2    ][brow] = make_uint2(h01, l01);
            Bsh[acb * 2 + 1][brow] = make_uint2(h23, l23);
        }
        __syncthreads();

        if (k0 + 16 < K) LOAD_T(k0 + 16)

        uint2 a0[2], a1[2], a2[2], a3[2];
#pragma unroll
        for (int mf = 0; mf < 2; mf++) {
            int mm = wm * 32 + mf * 16 + gid;
            a0[mf] = Ash[t4    ][mm];
            a1[mf] = Ash[t4    ][mm + 8];
            a2[mf] = Ash[t4 + 4][mm];
            a3[mf] = Ash[t4 + 4][mm + 8];
        }
#pragma unroll
        for (int nf = 0; nf < 4; nf++) {
            int nn = wn * 32 + nf * 8 + gid;
            uint2 b0 = Bsh[t4    ][nn];
            uint2 b1 = Bsh[t4 + 4][nn];
#pragma unroll
            for (int mf = 0; mf < 2; mf++) {
                mma_bf16(acc[mf][nf], a0[mf].x, a1[mf].x, a2[mf].x, a3[mf].x, b0.x, b1.x);
                mma_bf16(acc[mf][nf], a0[mf].y, a1[mf].y, a2[mf].y, a3[mf].y, b0.x, b1.x);
                mma_bf16(acc[mf][nf], a0[mf].x, a1[mf].x, a2[mf].x, a3[mf].x, b0.y, b1.y);
            }
        }
        __syncthreads();
    }

#pragma unroll
    for (int mf = 0; mf < 2; mf++)
#pragma unroll
        for (int nf = 0; nf < 4; nf++) {
            int r0 = m0 + wm * 32 + mf * 16 + gid;
            int c0 = n0 + wn * 32 + nf * 8 + 2 * t4;
#pragma unroll
            for (int q = 0; q < 4; q++) {
                int r = r0 + ((q >= 2) ? 8 : 0);
                int c = c0 + (q & 1);
                C[(size_t)r * ldc + c] = acc[mf][nf][q] + bias1[c] + bias2[c];
            }
        }
#undef LOAD_T
}

// ---------------- FC GEMM (tf32 single): permuted store ----------------------
template<int BM, int BN, int WM, int WN>
__global__ void __launch_bounds__(WM * WN * 32)
gemm_fc(const float* __restrict__ A, int M, int lda,
        const float* __restrict__ Bm, int N, int ldb, int K,
        const float* __restrict__ bias1,
        float* __restrict__ C, int ldc)
{
    constexpr int THREADS = WM * WN * 32;
    constexpr int PAD = 4;
    constexpr int MF = 2, NF = 4;

    __shared__ unsigned Ash[16][BM + PAD];
    __shared__ unsigned Bsh[16][BN + PAD];

    const int tid  = threadIdx.x;
    const int lane = tid & 31;
    const int warp = tid >> 5;
    const int wn = warp % WN, wm = warp / WN;
    const int gid = lane >> 2, t4 = lane & 3;
    const int m0 = blockIdx.x * BM;
    const int n0 = blockIdx.y * BN;

    float acc[MF][NF][4];
#pragma unroll
    for (int i = 0; i < MF; i++)
#pragma unroll
        for (int j = 0; j < NF; j++)
#pragma unroll
            for (int q = 0; q < 4; q++) acc[i][j][q] = 0.f;

    constexpr int LA = (BM * 16) / (THREADS * 4);
    constexpr int LB = (BN * 16) / (THREADS * 4);

    float4 ra[LA], rb[LB];

#define LOAD_T(K0)                                                          \
    {                                                                       \
        _Pragma("unroll")                                                   \
        for (int i = 0; i < LA; i++) {                                      \
            int f4 = tid + i * THREADS;                                     \
            int row = f4 >> 2, cb = f4 & 3;                                 \
            int gm = m0 + row;                                              \
            ra[i] = make_float4(0.f, 0.f, 0.f, 0.f);                        \
            if (gm < M) ra[i] = *(const float4*)(A + (size_t)gm * lda + (K0) + cb * 4); \
        }                                                                   \
        _Pragma("unroll")                                                   \
        for (int i = 0; i < LB; i++) {                                      \
            int f4 = tid + i * THREADS;                                     \
            int row = f4 >> 2, cb = f4 & 3;                                 \
            int grow = n0 + row;                                            \
            rb[i] = make_float4(0.f, 0.f, 0.f, 0.f);                        \
            if (grow < N) rb[i] = *(const float4*)(Bm + (size_t)grow * ldb + (K0) + cb * 4); \
        }                                                                   \
    }

    LOAD_T(0)

    for (int k0 = 0; k0 < K; k0 += 16) {
#pragma unroll
        for (int i = 0; i < LA; i++) {
            int f4 = tid + i * THREADS;
            int row = f4 >> 2, cb = f4 & 3;
            Ash[cb * 4 + 0][row] = f2t(ra[i].x);
            Ash[cb * 4 + 1][row] = f2t(ra[i].y);
            Ash[cb * 4 + 2][row] = f2t(ra[i].z);
            Ash[cb * 4 + 3][row] = f2t(ra[i].w);
        }
#pragma unroll
        for (int i = 0; i < LB; i++) {
            int f4 = tid + i * THREADS;
            int row = f4 >> 2, cb = f4 & 3;
            Bsh[cb * 4 + 0][row] = f2t(rb[i].x);
            Bsh[cb * 4 + 1][row] = f2t(rb[i].y);
            Bsh[cb * 4 + 2][row] = f2t(rb[i].z);
            Bsh[cb * 4 + 3][row] = f2t(rb[i].w);
        }
        __syncthreads();

        if (k0 + 16 < K) LOAD_T(k0 + 16)

#pragma unroll
        for (int ks = 0; ks < 2; ks++) {
            const int kb = ks * 8;
            unsigned ah[MF][4], bh[NF][2];
#pragma unroll
            for (int mf = 0; mf < MF; mf++) {
                int mm = wm * 32 + mf * 16 + gid;
                ah[mf][0] = Ash[kb + t4    ][mm];
                ah[mf][1] = Ash[kb + t4    ][mm + 8];
                ah[mf][2] = Ash[kb + t4 + 4][mm];
                ah[mf][3] = Ash[kb + t4 + 4][mm + 8];
            }
#pragma unroll
            for (int nf = 0; nf < NF; nf++) {
                int nn = wn * 32 + nf * 8 + gid;
                bh[nf][0] = Bsh[kb + t4    ][nn];
                bh[nf][1] = Bsh[kb + t4 + 4][nn];
            }
#pragma unroll
            for (int mf = 0; mf < MF; mf++)
#pragma unroll
                for (int nf = 0; nf < NF; nf++)
                    mma_tf32(acc[mf][nf], ah[mf], bh[nf]);
        }
        __syncthreads();
    }

#pragma unroll
    for (int mf = 0; mf < MF; mf++)
#pragma unroll
        for (int nf = 0; nf < NF; nf++) {
            int r0 = m0 + wm * 32 + mf * 16 + gid;
            int c0 = n0 + wn * 32 + nf * 8 + 2 * t4;
#pragma unroll
            for (int q = 0; q < 4; q++) {
                int r = r0 + ((q >= 2) ? 8 : 0);
                int c = c0 + (q & 1);
                if (r < M && c < N) {
                    int orow = (r & 127) * Ll + (r >> 7);
                    C[(size_t)orow * ldc + c] = acc[mf][nf][q] + bias1[c];
                }
            }
        }
#undef LOAD_T
}

// ---------------- in-place log_softmax, rows of 10000 ------------------------
__global__ void k_lsm(float* __restrict__ out) {
    __shared__ float row[Vv];
    __shared__ float red[8];
    float* p = out + (size_t)blockIdx.x * Vv;
    int tid = threadIdx.x;

    float mx = -1e30f;
    float4*       r4 = (float4*)row;
    const float4* p4 = (const float4*)p;
    for (int i = tid; i < Vv / 4; i += 256) {
        float4 v = p4[i];
        r4[i] = v;
        mx = fmaxf(mx, fmaxf(fmaxf(v.x, v.y), fmaxf(v.z, v.w)));
    }
#pragma unroll
    for (int o = 16; o > 0; o >>= 1) mx = fmaxf(mx, __shfl_xor_sync(0xffffffffu, mx, o));
    if ((tid & 31) == 0) red[tid >> 5] = mx;
    __syncthreads();
    mx = red[0];
#pragma unroll
    for (int i = 1; i < 8; i++) mx = fmaxf(mx, red[i]);

    float s = 0.f;
    for (int i = tid; i < Vv; i += 256) s += expf(row[i] - mx);
#pragma unroll
    for (int o = 16; o > 0; o >>= 1) s += __shfl_xor_sync(0xffffffffu, s, o);
    __syncthreads();
    if ((tid & 31) == 0) red[tid >> 5] = s;
    __syncthreads();
    s = red[0] + red[1] + red[2] + red[3] + red[4] + red[5] + red[6] + red[7];
    float lse = mx + logf(s);

    for (int i = tid; i < Vv; i += 256) p[i] = row[i] - lse;
}

// ---------------- host launcher ----------------------------------------------
extern "C" void kernel_launch(void* const* d_in, const int* in_sizes, int n_in,
                              void* d_out, int out_size) {
    const float* features = (const float*)d_in[0];
    const void*  caption  = d_in[1];
    const float* embW     = (const float*)d_in[2];
    const float* Wih      = (const float*)d_in[3];
    const float* Whh      = (const float*)d_in[4];
    const float* bih      = (const float*)d_in[5];
    const float* bhh      = (const float*)d_in[6];
    const float* lng      = (const float*)d_in[7];
    const float* lnb      = (const float*)d_in[8];
    const float* fcW      = (const float*)d_in[9];
    const float* fcb      = (const float*)d_in[10];
    float*       out      = (float*)d_out;

    float *pX, *pGx, *pH;
    cudaGetSymbolAddress((void**)&pX,  g_X);
    cudaGetSymbolAddress((void**)&pGx, g_Gx);
    cudaGetSymbolAddress((void**)&pH,  g_H);

    cudaFuncSetAttribute(k_recurrence,
                         cudaFuncAttributeMaxDynamicSharedMemorySize, SMEM_REC);

    k_init<<<256, 256>>>();
    k_detect<<<1, 256>>>((const int*)caption);
    k_build_x<<<Tt * Bn, 128>>>(features, caption, embW);

    // Gx = X @ Wih^T + bih + bhh   (both layers, bf16x3)
    for (int l = 0; l < 2; l++)
        gemm_gx_bf16<<<dim3(33, 32), 256>>>(
            pX, Tt * Bn, Dd,
            Wih + (size_t)l * G4 * Dd, G4, Dd, Dd,
            bih + l * G4, bhh + l * G4,
            pGx + (size_t)l * Tt * Bn * G4, G4);

    // full 33-step recurrence in ONE persistent kernel (single wave)
    k_recurrence<<<128, 256, SMEM_REC>>>(Whh, lng, lnb);

    // FC: logits = H @ fcW^T + fcb  (single tf32, permuted store)
    gemm_fc<128, 64, 4, 2><<<dim3(32, 157), 256>>>(
        pH, Ll * Bn, Dd, fcW, Vv, Dd, Dd,
        fcb, out, Vv);

    k_lsm<<<Ll * Bn, 256>>>(out);
}

// round 12
// speedup vs baseline: 1.3937x; 1.1906x over previous
#include <cuda_runtime.h>
#include <math.h>
#include <stdint.h>

#define Bn   128
#define Dd   512
#define Tt   33
#define Ll   32
#define Vv   10000
#define G4   2048

// ---------------- static device scratch ------------------------------------
__device__ float    g_X  [Tt * Bn * Dd];        // per-step inputs
__device__ float    g_Gx [2 * Tt * Bn * G4];    // x-side gates (both layers)
__device__ float    g_H  [Ll * Bn * Dd];        // normalized h history
__device__ float    g_h  [Bn * Dd];             // carried h (normalized)
__device__ float    g_hm [Bn * Dd];             // h after layer 0
__device__ float    g_hr [Bn * Dd];             // h after layer 1 (pre-LN)
__device__ __align__(128) unsigned g_bar0;      // group-0 barrier counter
__device__ __align__(128) unsigned g_bar1;      // group-1 barrier counter (own line)
__device__ int      g_cap64;

// ---------------- utility kernels -------------------------------------------
__global__ void k_init() {
    int i = blockIdx.x * blockDim.x + threadIdx.x;
    if (i < Bn * Dd) g_h[i] = 0.f;
    if (i == 0) { g_bar0 = 0u; g_bar1 = 0u; }
}

// caption int64 vs int32 detection (values < 10000 => int64 high words all 0)
__global__ void k_detect(const int* __restrict__ cap) {
    int any = 0;
    for (int i = threadIdx.x; i < 2048; i += blockDim.x)
        if (cap[2 * i + 1] != 0) any = 1;
    any = __syncthreads_or(any);
    if (threadIdx.x == 0) g_cap64 = any ? 0 : 1;
}

__global__ void k_build_x(const float* __restrict__ features,
                          const void*  __restrict__ cap,
                          const float* __restrict__ embW) {
    int blk = blockIdx.x;
    int t = blk >> 7;
    int b = blk & 127;
    const float* src;
    if (t == 0) {
        src = features + (size_t)b * Dd;
    } else {
        long long idx;
        if (g_cap64) idx = ((const long long*)cap)[b * Ll + (t - 1)];
        else         idx = (long long)((const int*)cap)[b * Ll + (t - 1)];
        src = embW + (size_t)idx * Dd;
    }
    float4*       dst = (float4*)(g_X + ((size_t)t * Bn + b) * Dd);
    const float4* s4  = (const float4*)src;
    dst[threadIdx.x] = s4[threadIdx.x];
}

// ---------------- tf32 helpers (FC path) -------------------------------------
__device__ __forceinline__ unsigned f2t(float x) {
    unsigned r;
    asm("cvt.rna.tf32.f32 %0, %1;" : "=r"(r) : "f"(x));
    return r;
}

__device__ __forceinline__ void mma_tf32(float* c, const unsigned* a, const unsigned* b) {
    asm volatile(
        "mma.sync.aligned.m16n8k8.row.col.f32.tf32.tf32.f32 "
        "{%0,%1,%2,%3}, {%4,%5,%6,%7}, {%8,%9}, {%0,%1,%2,%3};\n"
        : "+f"(c[0]), "+f"(c[1]), "+f"(c[2]), "+f"(c[3])
        : "r"(a[0]), "r"(a[1]), "r"(a[2]), "r"(a[3]), "r"(b[0]), "r"(b[1]));
}

// ---------------- bf16 helpers -------------------------------------------------
// pack: e0 -> low half, e1 -> high half
__device__ __forceinline__ unsigned bpack(float e0, float e1) {
    unsigned r;
    asm("cvt.rn.bf16x2.f32 %0, %1, %2;" : "=r"(r) : "f"(e1), "f"(e0));
    return r;
}
__device__ __forceinline__ float blo(unsigned p) { return __uint_as_float(p << 16); }
__device__ __forceinline__ float bhi(unsigned p) { return __uint_as_float(p & 0xffff0000u); }

__device__ __forceinline__ void mma_bf16(float* c,
                                         unsigned a0, unsigned a1, unsigned a2, unsigned a3,
                                         unsigned b0, unsigned b1) {
    asm volatile(
        "mma.sync.aligned.m16n8k16.row.col.f32.bf16.bf16.f32 "
        "{%0,%1,%2,%3}, {%4,%5,%6,%7}, {%8,%9}, {%0,%1,%2,%3};\n"
        : "+f"(c[0]), "+f"(c[1]), "+f"(c[2]), "+f"(c[3])
        : "r"(a0), "r"(a1), "r"(a2), "r"(a3), "r"(b0), "r"(b1));
}

__device__ __forceinline__ void ldsm4(unsigned& r0, unsigned& r1,
                                      unsigned& r2, unsigned& r3, unsigned addr) {
    asm volatile("ldmatrix.sync.aligned.m8n8.x4.shared.b16 {%0,%1,%2,%3}, [%4];"
                 : "=r"(r0), "=r"(r1), "=r"(r2), "=r"(r3) : "r"(addr));
}

// ---------------- fast activations (saturation-safe) -------------------------
__device__ __forceinline__ float fsig(float x) {
    float e = __expf(-x);
    return __fdividef(1.f, 1.f + e);
}
__device__ __forceinline__ float ftanh(float x) {
    float e = __expf(2.f * x);
    return 1.f - __fdividef(2.f, e + 1.f);
}

// ---------------- fence-free per-group grid barrier (64 arrivals) ------------
__device__ __forceinline__ void grid_barrier(unsigned* bar, unsigned& target) {
    __syncthreads();
    if (threadIdx.x == 0) {
        target += 64u;
        asm volatile("red.release.gpu.global.add.u32 [%0], 1;" :: "l"(bar) : "memory");
        unsigned v;
        do {
            asm volatile("ld.acquire.gpu.global.u32 %0, [%1];" : "=r"(v) : "l"(bar) : "memory");
        } while (v < target);
    }
    __syncthreads();
}

// ---------------- persistent recurrence kernel -------------------------------
// 128 CTAs x 256 threads = 2 independent batch-groups (64 rows) x 64 j-groups.
// Whh (both layers) resident in smem as bf16 hi/lo, row stride 1040 B
// (= 16 mod 128 -> 8 consecutive rows hit 8 distinct bank groups: ldmatrix
// conflict-free). A staged per half-K, row stride 528 B (same property).
// smem layout (bytes):
//   Bhi  bf16[2*32][520]    0      .. 66560
//   Blo  bf16[2*32][520]    66560  .. 133120
//   Ahi  bf16[64][264]      133120 .. 166912   } Cs float[64][36] unions at
//   Alo  bf16[64][264]      166912 .. 200704   } 133120 (used post-mma only)
//   csm  float[64][8]       200704 .. 202752
//   red  float[8]           202752 .. 202784
#define SM_BHI  0
#define SM_BLO  66560
#define SM_AHI  133120
#define SM_ALO  166912
#define SM_CS   133120
#define SM_CSM  200704
#define SM_RED  202752
#define SMEM_REC 202784
#define A_STRIDE 528            // bytes per A row (264 bf16)
#define B_STRIDE 1040           // bytes per B row (520 bf16)
#define B_LAYER  (32 * B_STRIDE)

__global__ void __launch_bounds__(256, 1)
k_recurrence(const float* __restrict__ Whh,
             const float* __restrict__ lng, const float* __restrict__ lnb) {
    extern __shared__ __align__(16) char sbuf[];
    const unsigned sbase = (unsigned)__cvta_generic_to_shared(sbuf);
    float (*Cs)[36]  = (float(*)[36])(sbuf + SM_CS);
    float (*csm)[8]  = (float(*)[8])(sbuf + SM_CSM);
    float* red       = (float*)(sbuf + SM_RED);

    const int tid  = threadIdx.x;
    const int lane = tid & 31;
    const int warp = tid >> 5;
    const int t4   = lane & 3;
    const int gid  = lane >> 2;
    const int cta  = blockIdx.x;             // 0..127
    const int jcta = cta & 63;               // j-group: cols [jcta*8, jcta*8+8)
    const int grp  = cta >> 6;               // batch group 0/1
    const int bm0  = grp * 64;               // batch-group base row
    const int wm   = warp >> 1, wn = warp & 1;  // 4x2 warps, warp tile 16x16
    unsigned* mybar = grp ? &g_bar1 : &g_bar0;
    unsigned target = 0;
    (void)t4; (void)gid;

    // ---- one-time: Whh slice (both layers) -> bf16 hi/lo in smem ----------
    // gate-interleaved row p = jcta*32 + rl  <->  original row ((p&3)<<9)|(p>>2)
    for (int idx = tid; idx < 2 * 32 * 256; idx += 256) {
        int l  = idx >> 13;
        int rm = idx & 8191;
        int rl = rm >> 8;                    // local row 0..31
        int kp = rm & 255;                   // k-pair 0..255
        int p  = jcta * 32 + rl;
        int orig = ((p & 3) << 9) | (p >> 2);
        float2 v = *(const float2*)(Whh + ((size_t)l * G4 + orig) * Dd + kp * 2);
        unsigned h  = bpack(v.x, v.y);
        unsigned lo = bpack(v.x - blo(h), v.y - bhi(h));
        size_t roff = (size_t)(l * 32 + rl) * B_STRIDE + kp * 4;
        *(unsigned*)(sbuf + SM_BHI + roff) = h;
        *(unsigned*)(sbuf + SM_BLO + roff) = lo;
    }
    for (int i = tid; i < 64 * 8; i += 256) csm[i >> 3][i & 7] = 0.f;
    float lg0 = lng[tid], lg1 = lng[tid + 256];
    float lb0 = lnb[tid], lb1 = lnb[tid + 256];
    __syncthreads();

    // ---- ldmatrix lane address bases (constant across phases) -------------
    // A x4 matrices: {m0-7/k0-7, m8-15/k0-7, m0-7/k8-15, m8-15/k8-15}
    // B x4 matrices: {n0-7/k0-7, n0-7/k8-15, n8-15/k0-7, n8-15/k8-15}
    const int sel = lane >> 3, lr = lane & 7;
    const unsigned aHiBase = sbase + SM_AHI
        + (unsigned)((wm * 16 + (sel & 1) * 8 + lr) * A_STRIDE + (sel >> 1) * 16);
    const unsigned aLoBase = aHiBase + (SM_ALO - SM_AHI);
    const unsigned bLaneOff =
        (unsigned)((wn * 16 + (sel >> 1) * 8 + lr) * B_STRIDE + (sel & 1) * 16);

    float gpre[2][4];
#define GXLOAD(TT, LL)                                                    \
    {                                                                     \
        const float* gxp = g_Gx + ((size_t)(LL) * Tt + (TT)) * Bn * G4;   \
        _Pragma("unroll")                                                 \
        for (int it = 0; it < 2; it++) {                                  \
            int x = tid + it * 256;                                       \
            int b = bm0 + (x >> 3);                                       \
            int j = jcta * 8 + (x & 7);                                   \
            gpre[it][0] = __ldg(&gxp[b * G4 + j]);                        \
            gpre[it][1] = __ldg(&gxp[b * G4 + 512 + j]);                  \
            gpre[it][2] = __ldg(&gxp[b * G4 + 1024 + j]);                 \
            gpre[it][3] = __ldg(&gxp[b * G4 + 1536 + j]);                 \
        }                                                                 \
    }

    GXLOAD(0, 0)

    for (int t = 0; t < Tt; t++) {
#pragma unroll 1
        for (int l = 0; l < 2; l++) {
            const float* A    = (l == 0) ? g_h : g_hm;
            float*       hout = (l == 0) ? g_hm : g_hr;
            const unsigned bHiP = sbase + SM_BHI + l * B_LAYER + bLaneOff;
            const unsigned bLoP = bHiP + (SM_BLO - SM_BHI);

            float accA[2][4], accB[2][4];
#pragma unroll
            for (int n = 0; n < 2; n++)
#pragma unroll
                for (int q = 0; q < 4; q++) { accA[n][q] = 0.f; accB[n][q] = 0.f; }

#pragma unroll 1
            for (int half = 0; half < 2; half++) {
                // ---- stage A half: 64 rows x 256 k -> bf16 hi/lo ----
                const float* Ag = A + (size_t)bm0 * Dd + half * 256;
#pragma unroll
                for (int r = 0; r < 16; r++) {
                    int idx = tid + r * 256;
                    int row = idx >> 6, c4 = idx & 63;
                    float4 v = __ldcg((const float4*)(Ag + (size_t)row * Dd + c4 * 4));
                    unsigned h01 = bpack(v.x, v.y);
                    unsigned h23 = bpack(v.z, v.w);
                    unsigned l01 = bpack(v.x - blo(h01), v.y - bhi(h01));
                    unsigned l23 = bpack(v.z - blo(h23), v.w - bhi(h23));
                    size_t off = (size_t)row * A_STRIDE + c4 * 8;
                    *(uint2*)(sbuf + SM_AHI + off) = make_uint2(h01, h23);
                    *(uint2*)(sbuf + SM_ALO + off) = make_uint2(l01, l23);
                }
                __syncthreads();

                const unsigned bOff = half * 512;   // k bytes into B rows
#pragma unroll
                for (int i = 0; i < 16; i++) {
                    unsigned ah0, ah1, ah2, ah3, al0, al1, al2, al3;
                    unsigned bh0, bh1, bh2, bh3, bl0, bl1, bl2, bl3;
                    ldsm4(ah0, ah1, ah2, ah3, aHiBase + i * 32);
                    ldsm4(al0, al1, al2, al3, aLoBase + i * 32);
                    ldsm4(bh0, bh1, bh2, bh3, bHiP + bOff + i * 32);
                    ldsm4(bl0, bl1, bl2, bl3, bLoP + bOff + i * 32);
                    mma_bf16(accA[0], ah0, ah1, ah2, ah3, bh0, bh1);  // hi.hi n0
                    mma_bf16(accB[0], al0, al1, al2, al3, bh0, bh1);  // lo.hi n0
                    mma_bf16(accB[0], ah0, ah1, ah2, ah3, bl0, bl1);  // hi.lo n0
                    mma_bf16(accA[1], ah0, ah1, ah2, ah3, bh2, bh3);  // hi.hi n1
                    mma_bf16(accB[1], al0, al1, al2, al3, bh2, bh3);  // lo.hi n1
                    mma_bf16(accB[1], ah0, ah1, ah2, ah3, bl2, bl3);  // hi.lo n1
                }
                __syncthreads();
            }
            // accumulators -> Cs (unions A staging; safe after sync)
#pragma unroll
            for (int nf = 0; nf < 2; nf++) {
                int r0 = wm * 16 + gid;
                int c0 = wn * 16 + nf * 8 + 2 * t4;
                Cs[r0    ][c0    ] = accA[nf][0] + accB[nf][0];
                Cs[r0    ][c0 + 1] = accA[nf][1] + accB[nf][1];
                Cs[r0 + 8][c0    ] = accA[nf][2] + accB[nf][2];
                Cs[r0 + 8][c0 + 1] = accA[nf][3] + accB[nf][3];
            }
            __syncthreads();
            // LSTM cell: 64x8 = 512 elements, 2 per thread (gx preloaded)
#pragma unroll
            for (int it = 0; it < 2; it++) {
                int x    = tid + it * 256;
                int brow = x >> 3, jj = x & 7;
                int b    = bm0 + brow;
                int j    = jcta * 8 + jj;
                float gi = Cs[brow][jj * 4 + 0] + gpre[it][0];
                float gf = Cs[brow][jj * 4 + 1] + gpre[it][1];
                float gg = Cs[brow][jj * 4 + 2] + gpre[it][2];
                float go = Cs[brow][jj * 4 + 3] + gpre[it][3];
                float ii = fsig(gi);
                float ff = fsig(gf);
                float gt = ftanh(gg);
                float oo = fsig(go);
                float cn = ff * csm[brow][jj] + ii * gt;
                csm[brow][jj] = cn;
                __stcg(&hout[(size_t)b * Dd + j], oo * ftanh(cn));
            }
            // hoist next phase's gx loads across the barrier (static data)
            if (l == 0) { GXLOAD(t, 1) }
            else if (t + 1 < Tt) { GXLOAD(t + 1, 0) }
            grid_barrier(mybar, target);
        }
        // ---- LayerNorm: CTA handles batch row b = cta (256 threads, 2 elems) --
        {
            const float* xr = g_hr + (size_t)cta * Dd;
            float v0 = __ldcg(&xr[tid]), v1 = __ldcg(&xr[tid + 256]);
            float s = v0 + v1;
#pragma unroll
            for (int o = 16; o > 0; o >>= 1) s += __shfl_xor_sync(0xffffffffu, s, o);
            if (lane == 0) red[warp] = s;
            __syncthreads();
            float mu = (red[0] + red[1] + red[2] + red[3] +
                        red[4] + red[5] + red[6] + red[7]) * (1.f / 512.f);
            __syncthreads();
            float d0 = v0 - mu, d1 = v1 - mu;
            float vv = d0 * d0 + d1 * d1;
#pragma unroll
            for (int o = 16; o > 0; o >>= 1) vv += __shfl_xor_sync(0xffffffffu, vv, o);
            if (lane == 0) red[warp] = vv;
            __syncthreads();
            float var  = (red[0] + red[1] + red[2] + red[3] +
                          red[4] + red[5] + red[6] + red[7]) * (1.f / 512.f);
            float rstd = rsqrtf(var + 1e-5f);
            float y0 = d0 * rstd * lg0 + lb0;
            float y1 = d1 * rstd * lg1 + lb1;
            __stcg(&g_h[(size_t)cta * Dd + tid],       y0);
            __stcg(&g_h[(size_t)cta * Dd + tid + 256], y1);
            if (t > 0) {
                g_H[((size_t)(t - 1) * Bn + cta) * Dd + tid]       = y0;
                g_H[((size_t)(t - 1) * Bn + cta) * Dd + tid + 256] = y1;
            }
            __syncthreads();
        }
        grid_barrier(mybar, target);
    }
#undef GXLOAD
}

// ---------------- Gx GEMM, bf16x3:  C = A(MxK) * B(NxK)^T + b1 + b2 ----------
// BM=128, BN=64, 256 threads, warp tile 32x32, k-tile 16 (8 bf16 pairs).
__global__ void __launch_bounds__(256)
gemm_gx_bf16(const float* __restrict__ A, int M, int lda,
             const float* __restrict__ Bm, int N, int ldb, int K,
             const float* __restrict__ bias1, const float* __restrict__ bias2,
             float* __restrict__ C, int ldc)
{
    __shared__ uint2 Ash[8][132];
    __shared__ uint2 Bsh[8][68];

    const int tid  = threadIdx.x;
    const int lane = tid & 31;
    const int warp = tid >> 5;
    const int wn = warp & 1, wm = warp >> 1;   // 4x2 warps
    const int gid = lane >> 2, t4 = lane & 3;
    const int m0 = blockIdx.x * 128;
    const int n0 = blockIdx.y * 64;

    float acc[2][4][4];
#pragma unroll
    for (int i = 0; i < 2; i++)
#pragma unroll
        for (int j = 0; j < 4; j++)
#pragma unroll
            for (int q = 0; q < 4; q++) acc[i][j][q] = 0.f;

    float4 ra[2], rb;
    const int arow = tid >> 2,  acb = tid & 3;
    const int brow = (tid & 255) >> 2;
#define LOAD_T(K0)                                                           \
    {                                                                        \
        ra[0] = *(const float4*)(A + (size_t)(m0 + arow) * lda + (K0) + acb * 4);       \
        ra[1] = *(const float4*)(A + (size_t)(m0 + arow + 64) * lda + (K0) + acb * 4);  \
        rb    = *(const float4*)(Bm + (size_t)(n0 + brow) * ldb + (K0) + acb * 4);      \
    }

    LOAD_T(0)

    for (int k0 = 0; k0 < K; k0 += 16) {
#pragma unroll
        for (int i = 0; i < 2; i++) {
            unsigned h01 = bpack(ra[i].x, ra[i].y);
            unsigned h23 = bpack(ra[i].z, ra[i].w);
            unsigned l01 = bpack(ra[i].x - blo(h01), ra[i].y - bhi(h01));
            unsigned l23 = bpack(ra[i].z - blo(h23), ra[i].w - bhi(h23));
            Ash[acb * 2    ][arow + i * 64] = make_uint2(h01, l01);
            Ash[acb * 2 + 1][arow + i * 64] = make_uint2(h23, l23);
        }
        {
            unsigned h01 = bpack(rb.x, rb.y);
            unsigned h23 = bpack(rb.z, rb.w);
            unsigned l01 = bpack(rb.x - blo(h01), rb.y - bhi(h01));
            unsigned l23 = bpack(rb.z - blo(h23), rb.w - bhi(h23));
            Bsh[acb * 2    ][brow] = make_uint2(h01, l01);
            Bsh[acb * 2 + 1][brow] = make_uint2(h23, l23);
        }
        __syncthreads();

        if (k0 + 16 < K) LOAD_T(k0 + 16)

        uint2 a0[2], a1[2], a2[2], a3[2];
#pragma unroll
        for (int mf = 0; mf < 2; mf++) {
            int mm = wm * 32 + mf * 16 + gid;
            a0[mf] = Ash[t4    ][mm];
            a1[mf] = Ash[t4    ][mm + 8];
            a2[mf] = Ash[t4 + 4][mm];
            a3[mf] = Ash[t4 + 4][mm + 8];
        }
#pragma unroll
        for (int nf = 0; nf < 4; nf++) {
            int nn = wn * 32 + nf * 8 + gid;
            uint2 b0 = Bsh[t4    ][nn];
            uint2 b1 = Bsh[t4 + 4][nn];
#pragma unroll
            for (int mf = 0; mf < 2; mf++) {
                mma_bf16(acc[mf][nf], a0[mf].x, a1[mf].x, a2[mf].x, a3[mf].x, b0.x, b1.x);
                mma_bf16(acc[mf][nf], a0[mf].y, a1[mf].y, a2[mf].y, a3[mf].y, b0.x, b1.x);
                mma_bf16(acc[mf][nf], a0[mf].x, a1[mf].x, a2[mf].x, a3[mf].x, b0.y, b1.y);
            }
        }
        __syncthreads();
    }

#pragma unroll
    for (int mf = 0; mf < 2; mf++)
#pragma unroll
        for (int nf = 0; nf < 4; nf++) {
            int r0 = m0 + wm * 32 + mf * 16 + gid;
            int c0 = n0 + wn * 32 + nf * 8 + 2 * t4;
#pragma unroll
            for (int q = 0; q < 4; q++) {
                int r = r0 + ((q >= 2) ? 8 : 0);
                int c = c0 + (q & 1);
                C[(size_t)r * ldc + c] = acc[mf][nf][q] + bias1[c] + bias2[c];
            }
        }
#undef LOAD_T
}

// ---------------- FC GEMM (tf32 single): permuted store ----------------------
template<int BM, int BN, int WM, int WN>
__global__ void __launch_bounds__(WM * WN * 32)
gemm_fc(const float* __restrict__ A, int M, int lda,
        const float* __restrict__ Bm, int N, int ldb, int K,
        const float* __restrict__ bias1,
        float* __restrict__ C, int ldc)
{
    constexpr int THREADS = WM * WN * 32;
    constexpr int PAD = 4;
    constexpr int MF = 2, NF = 4;

    __shared__ unsigned Ash[16][BM + PAD];
    __shared__ unsigned Bsh[16][BN + PAD];

    const int tid  = threadIdx.x;
    const int lane = tid & 31;
    const int warp = tid >> 5;
    const int wn = warp % WN, wm = warp / WN;
    const int gid = lane >> 2, t4 = lane & 3;
    const int m0 = blockIdx.x * BM;
    const int n0 = blockIdx.y * BN;

    float acc[MF][NF][4];
#pragma unroll
    for (int i = 0; i < MF; i++)
#pragma unroll
        for (int j = 0; j < NF; j++)
#pragma unroll
            for (int q = 0; q < 4; q++) acc[i][j][q] = 0.f;

    constexpr int LA = (BM * 16) / (THREADS * 4);
    constexpr int LB = (BN * 16) / (THREADS * 4);

    float4 ra[LA], rb[LB];

#define LOAD_T(K0)                                                          \
    {                                                                       \
        _Pragma("unroll")                                                   \
        for (int i = 0; i < LA; i++) {                                      \
            int f4 = tid + i * THREADS;                                     \
            int row = f4 >> 2, cb = f4 & 3;                                 \
            int gm = m0 + row;                                              \
            ra[i] = make_float4(0.f, 0.f, 0.f, 0.f);                        \
            if (gm < M) ra[i] = *(const float4*)(A + (size_t)gm * lda + (K0) + cb * 4); \
        }                                                                   \
        _Pragma("unroll")                                                   \
        for (int i = 0; i < LB; i++) {                                      \
            int f4 = tid + i * THREADS;                                     \
            int row = f4 >> 2, cb = f4 & 3;                                 \
            int grow = n0 + row;                                            \
            rb[i] = make_float4(0.f, 0.f, 0.f, 0.f);                        \
            if (grow < N) rb[i] = *(const float4*)(Bm + (size_t)grow * ldb + (K0) + cb * 4); \
        }                                                                   \
    }

    LOAD_T(0)

    for (int k0 = 0; k0 < K; k0 += 16) {
#pragma unroll
        for (int i = 0; i < LA; i++) {
            int f4 = tid + i * THREADS;
            int row = f4 >> 2, cb = f4 & 3;
            Ash[cb * 4 + 0][row] = f2t(ra[i].x);
            Ash[cb * 4 + 1][row] = f2t(ra[i].y);
            Ash[cb * 4 + 2][row] = f2t(ra[i].z);
            Ash[cb * 4 + 3][row] = f2t(ra[i].w);
        }
#pragma unroll
        for (int i = 0; i < LB; i++) {
            int f4 = tid + i * THREADS;
            int row = f4 >> 2, cb = f4 & 3;
            Bsh[cb * 4 + 0][row] = f2t(rb[i].x);
            Bsh[cb * 4 + 1][row] = f2t(rb[i].y);
            Bsh[cb * 4 + 2][row] = f2t(rb[i].z);
            Bsh[cb * 4 + 3][row] = f2t(rb[i].w);
        }
        __syncthreads();

        if (k0 + 16 < K) LOAD_T(k0 + 16)

#pragma unroll
        for (int ks = 0; ks < 2; ks++) {
            const int kb = ks * 8;
            unsigned ah[MF][4], bh[NF][2];
#pragma unroll
            for (int mf = 0; mf < MF; mf++) {
                int mm = wm * 32 + mf * 16 + gid;
                ah[mf][0] = Ash[kb + t4    ][mm];
                ah[mf][1] = Ash[kb + t4    ][mm + 8];
                ah[mf][2] = Ash[kb + t4 + 4][mm];
                ah[mf][3] = Ash[kb + t4 + 4][mm + 8];
            }
#pragma unroll
            for (int nf = 0; nf < NF; nf++) {
                int nn = wn * 32 + nf * 8 + gid;
                bh[nf][0] = Bsh[kb + t4    ][nn];
                bh[nf][1] = Bsh[kb + t4 + 4][nn];
            }
#pragma unroll
            for (int mf = 0; mf < MF; mf++)
#pragma unroll
                for (int nf = 0; nf < NF; nf++)
                    mma_tf32(acc[mf][nf], ah[mf], bh[nf]);
        }
        __syncthreads();
    }

#pragma unroll
    for (int mf = 0; mf < MF; mf++)
#pragma unroll
        for (int nf = 0; nf < NF; nf++) {
            int r0 = m0 + wm * 32 + mf * 16 + gid;
            int c0 = n0 + wn * 32 + nf * 8 + 2 * t4;
#pragma unroll
            for (int q = 0; q < 4; q++) {
                int r = r0 + ((q >= 2) ? 8 : 0);
                int c = c0 + (q & 1);
                if (r < M && c < N) {
                    int orow = (r & 127) * Ll + (r >> 7);
                    C[(size_t)orow * ldc + c] = acc[mf][nf][q] + bias1[c];
                }
            }
        }
#undef LOAD_T
}

// ---------------- in-place log_softmax, rows of 10000 ------------------------
__global__ void k_lsm(float* __restrict__ out) {
    __shared__ float row[Vv];
    __shared__ float red[8];
    float* p = out + (size_t)blockIdx.x * Vv;
    int tid = threadIdx.x;

    float mx = -1e30f;
    float4*       r4 = (float4*)row;
    const float4* p4 = (const float4*)p;
    for (int i = tid; i < Vv / 4; i += 256) {
        float4 v = p4[i];
        r4[i] = v;
        mx = fmaxf(mx, fmaxf(fmaxf(v.x, v.y), fmaxf(v.z, v.w)));
    }
#pragma unroll
    for (int o = 16; o > 0; o >>= 1) mx = fmaxf(mx, __shfl_xor_sync(0xffffffffu, mx, o));
    if ((tid & 31) == 0) red[tid >> 5] = mx;
    __syncthreads();
    mx = red[0];
#pragma unroll
    for (int i = 1; i < 8; i++) mx = fmaxf(mx, red[i]);

    float s = 0.f;
    for (int i = tid; i < Vv; i += 256) s += expf(row[i] - mx);
#pragma unroll
    for (int o = 16; o > 0; o >>= 1) s += __shfl_xor_sync(0xffffffffu, s, o);
    __syncthreads();
    if ((tid & 31) == 0) red[tid >> 5] = s;
    __syncthreads();
    s = red[0] + red[1] + red[2] + red[3] + red[4] + red[5] + red[6] + red[7];
    float lse = mx + logf(s);

    for (int i = tid; i < Vv; i += 256) p[i] = row[i] - lse;
}

// ---------------- host launcher ----------------------------------------------
extern "C" void kernel_launch(void* const* d_in, const int* in_sizes, int n_in,
                              void* d_out, int out_size) {
    const float* features = (const float*)d_in[0];
    const void*  caption  = d_in[1];
    const float* embW     = (const float*)d_in[2];
    const float* Wih      = (const float*)d_in[3];
    const float* Whh      = (const float*)d_in[4];
    const float* bih      = (const float*)d_in[5];
    const float* bhh      = (const float*)d_in[6];
    const float* lng      = (const float*)d_in[7];
    const float* lnb      = (const float*)d_in[8];
    const float* fcW      = (const float*)d_in[9];
    const float* fcb      = (const float*)d_in[10];
    float*       out      = (float*)d_out;

    float *pX, *pGx, *pH;
    cudaGetSymbolAddress((void**)&pX,  g_X);
    cudaGetSymbolAddress((void**)&pGx, g_Gx);
    cudaGetSymbolAddress((void**)&pH,  g_H);

    cudaFuncSetAttribute(k_recurrence,
                         cudaFuncAttributeMaxDynamicSharedMemorySize, SMEM_REC);

    k_init<<<256, 256>>>();
    k_detect<<<1, 256>>>((const int*)caption);
    k_build_x<<<Tt * Bn, 128>>>(features, caption, embW);

    // Gx = X @ Wih^T + bih + bhh   (both layers, bf16x3)
    for (int l = 0; l < 2; l++)
        gemm_gx_bf16<<<dim3(33, 32), 256>>>(
            pX, Tt * Bn, Dd,
            Wih + (size_t)l * G4 * Dd, G4, Dd, Dd,
            bih + l * G4, bhh + l * G4,
            pGx + (size_t)l * Tt * Bn * G4, G4);

    // full 33-step recurrence in ONE persistent kernel (single wave)
    k_recurrence<<<128, 256, SMEM_REC>>>(Whh, lng, lnb);

    // FC: logits = H @ fcW^T + fcb  (single tf32, permuted store)
    gemm_fc<128, 64, 4, 2><<<dim3(32, 157), 256>>>(
        pH, Ll * Bn, Dd, fcW, Vv, Dd, Dd,
        fcb, out, Vv);

    k_lsm<<<Ll * Bn, 256>>>(out);
}